// round 1
// baseline (speedup 1.0000x reference)
#include <cuda_runtime.h>
#include <cuda_bf16.h>
#include <math.h>

// Problem constants
#define BATCH 4
#define T 1024
#define E 1024
#define NH 16
#define HS 64
#define HID 4096
#define M_ROWS (BATCH * T)   // 4096
#define LN_EPS 1e-5f
// scale applied to q and k each is E^-0.25 -> dot scaled by E^-0.5 = 1/32
#define ATT_SCALE 0.03125f

// ---------------------------------------------------------------------------
// Scratch (no cudaMalloc allowed) — __device__ globals
// ---------------------------------------------------------------------------
__device__ float g_q[M_ROWS * E];
__device__ float g_k[M_ROWS * E];
__device__ float g_v[M_ROWS * E];
__device__ float g_attn[M_ROWS * E];
__device__ float g_tmp[M_ROWS * E];
__device__ float g_x1[M_ROWS * E];
__device__ float g_x2[M_ROWS * E];
__device__ float g_ff[M_ROWS * HID];

// ---------------------------------------------------------------------------
// SGEMM: C[M,N] = A[M,K] @ B[K,N] (+bias) (+relu). Row-major everywhere.
// BM=BN=128, BK=8, 256 threads, 8x8 per-thread microtile.
// Requires M%128==0, N%128==0, K%8==0 (all shapes here satisfy this).
// ---------------------------------------------------------------------------
__global__ void __launch_bounds__(256)
sgemm_kernel(const float* __restrict__ A, const float* __restrict__ B,
             const float* __restrict__ bias, float* __restrict__ C,
             int M, int N, int K, int do_relu)
{
    const int BM = 128, BN = 128, BK = 8;
    __shared__ float As[BK][BM];
    __shared__ float Bs[BK][BN];

    int tid = threadIdx.x;
    int bx = blockIdx.x;   // N tile
    int by = blockIdx.y;   // M tile
    int tx = tid & 15;     // 0..15 -> col group
    int ty = tid >> 4;     // 0..15 -> row group

    const float* Ab = A + (size_t)by * BM * K;
    const float* Bb = B + (size_t)bx * BN;

    // A tile load: 128 rows x 8 cols = 256 float4
    int arow  = tid >> 1;
    int acol4 = (tid & 1) * 4;
    // B tile load: 8 rows x 128 cols = 256 float4
    int brow  = tid >> 5;
    int bcol4 = (tid & 31) * 4;

    float acc[8][8];
#pragma unroll
    for (int i = 0; i < 8; i++)
#pragma unroll
        for (int j = 0; j < 8; j++) acc[i][j] = 0.f;

    for (int k0 = 0; k0 < K; k0 += BK) {
        float4 a4 = *(const float4*)(Ab + (size_t)arow * K + k0 + acol4);
        As[acol4 + 0][arow] = a4.x;
        As[acol4 + 1][arow] = a4.y;
        As[acol4 + 2][arow] = a4.z;
        As[acol4 + 3][arow] = a4.w;
        float4 b4 = *(const float4*)(Bb + (size_t)(k0 + brow) * N + bcol4);
        *(float4*)&Bs[brow][bcol4] = b4;
        __syncthreads();

#pragma unroll
        for (int k = 0; k < BK; k++) {
            float4 ra0 = *(const float4*)&As[k][ty * 8];
            float4 ra1 = *(const float4*)&As[k][ty * 8 + 4];
            float4 rb0 = *(const float4*)&Bs[k][tx * 8];
            float4 rb1 = *(const float4*)&Bs[k][tx * 8 + 4];
            float ra[8] = {ra0.x, ra0.y, ra0.z, ra0.w, ra1.x, ra1.y, ra1.z, ra1.w};
            float rb[8] = {rb0.x, rb0.y, rb0.z, rb0.w, rb1.x, rb1.y, rb1.z, rb1.w};
#pragma unroll
            for (int i = 0; i < 8; i++)
#pragma unroll
                for (int j = 0; j < 8; j++)
                    acc[i][j] += ra[i] * rb[j];
        }
        __syncthreads();
    }

#pragma unroll
    for (int i = 0; i < 8; i++) {
        int row = by * BM + ty * 8 + i;
#pragma unroll
        for (int j = 0; j < 8; j += 4) {
            int col = bx * BN + tx * 8 + j;
            float4 v = make_float4(acc[i][j], acc[i][j + 1], acc[i][j + 2], acc[i][j + 3]);
            if (bias) {
                v.x += bias[col + 0];
                v.y += bias[col + 1];
                v.z += bias[col + 2];
                v.w += bias[col + 3];
            }
            if (do_relu) {
                v.x = fmaxf(v.x, 0.f);
                v.y = fmaxf(v.y, 0.f);
                v.z = fmaxf(v.z, 0.f);
                v.w = fmaxf(v.w, 0.f);
            }
            *(float4*)(C + (size_t)row * N + col) = v;
        }
    }
}

// ---------------------------------------------------------------------------
// Flash attention (fp32, online softmax).
// grid: (BATCH*NH, T/BR). block: BR=128 threads, one q-row per thread.
// Q/K/V are the [M_ROWS, E] projection buffers; head h lives in cols [h*64, h*64+64).
// ---------------------------------------------------------------------------
#define FA_BR 128
#define FA_BC 64

__global__ void __launch_bounds__(FA_BR)
flash_attn_kernel(const float* __restrict__ Q, const float* __restrict__ Km,
                  const float* __restrict__ Vm, float* __restrict__ O, int causal)
{
    __shared__ float smem[2 * FA_BC * HS];   // Ks | Vs (also q staging)
    float* Ks = smem;
    float* Vs = smem + FA_BC * HS;

    int bh = blockIdx.x;
    int b  = bh >> 4;       // NH = 16
    int h  = bh & 15;
    int qtile = blockIdx.y;
    int tid = threadIdx.x;
    int qi  = qtile * FA_BR + tid;   // local q row within [0, T)

    // Stage Q tile through shared (coalesced gmem), then scatter to registers
    float q[HS];
    {
        const float* Qg = Q + ((size_t)(b * T + qtile * FA_BR)) * E + h * HS;
        for (int i = tid; i < FA_BR * HS / 4; i += FA_BR) {
            int r = i >> 4;           // /16
            int c = i & 15;
            ((float4*)smem)[(size_t)r * 16 + c] = *(const float4*)(Qg + (size_t)r * E + c * 4);
        }
        __syncthreads();
#pragma unroll
        for (int d = 0; d < HS; d++) q[d] = smem[tid * HS + d];
        __syncthreads();
    }

    float o[HS];
#pragma unroll
    for (int d = 0; d < HS; d++) o[d] = 0.f;
    float m = -1e30f, l = 0.f;

    int ktiles = causal ? 2 * (qtile + 1) : (T / FA_BC);

    for (int kt = 0; kt < ktiles; kt++) {
        const float* Kg = Km + ((size_t)(b * T + kt * FA_BC)) * E + h * HS;
        const float* Vg = Vm + ((size_t)(b * T + kt * FA_BC)) * E + h * HS;
        for (int i = tid; i < FA_BC * HS / 4; i += FA_BR) {
            int r = i >> 4;
            int c = i & 15;
            ((float4*)Ks)[i] = *(const float4*)(Kg + (size_t)r * E + c * 4);
            ((float4*)Vs)[i] = *(const float4*)(Vg + (size_t)r * E + c * 4);
        }
        __syncthreads();

        int jmax = FA_BC;
        if (causal) {
            int rel = qi - kt * FA_BC;
            jmax = rel + 1;
            if (jmax > FA_BC) jmax = FA_BC;
            if (jmax < 0) jmax = 0;
        }

        for (int j = 0; j < jmax; j++) {
            const float4* kr = (const float4*)(Ks + j * HS);
            float s = 0.f;
#pragma unroll
            for (int d = 0; d < 16; d++) {
                float4 kv = kr[d];
                s += q[4 * d + 0] * kv.x + q[4 * d + 1] * kv.y
                   + q[4 * d + 2] * kv.z + q[4 * d + 3] * kv.w;
            }
            s *= ATT_SCALE;
            if (s > m) {
                float alpha = expf(m - s);   // expf(-inf)=0 handles first iter
                l *= alpha;
#pragma unroll
                for (int d = 0; d < HS; d++) o[d] *= alpha;
                m = s;
            }
            float p = expf(s - m);
            l += p;
            const float4* vr = (const float4*)(Vs + j * HS);
#pragma unroll
            for (int d = 0; d < 16; d++) {
                float4 vv = vr[d];
                o[4 * d + 0] += p * vv.x;
                o[4 * d + 1] += p * vv.y;
                o[4 * d + 2] += p * vv.z;
                o[4 * d + 3] += p * vv.w;
            }
        }
        __syncthreads();
    }

    float inv = 1.f / l;
    float* Og = O + ((size_t)(b * T + qi)) * E + h * HS;
#pragma unroll
    for (int d = 0; d < 16; d++) {
        float4 v = make_float4(o[4 * d] * inv, o[4 * d + 1] * inv,
                               o[4 * d + 2] * inv, o[4 * d + 3] * inv);
        *(float4*)(Og + 4 * d) = v;
    }
}

// ---------------------------------------------------------------------------
// Fused residual + LayerNorm: out = LN(x + r) * g + b.  One block per row.
// ---------------------------------------------------------------------------
__global__ void __launch_bounds__(256)
ln_residual_kernel(const float* __restrict__ X, const float* __restrict__ R,
                   const float* __restrict__ G, const float* __restrict__ Bt,
                   float* __restrict__ Out)
{
    const int N = E;
    int row = blockIdx.x;
    int tid = threadIdx.x;
    int lane = tid & 31, wid = tid >> 5;
    __shared__ float sm[8];
    __shared__ float stats[2];

    float v[4];
    float s = 0.f;
#pragma unroll
    for (int i = 0; i < 4; i++) {
        int idx = tid + i * 256;
        v[i] = X[(size_t)row * N + idx] + R[(size_t)row * N + idx];
        s += v[i];
    }
#pragma unroll
    for (int off = 16; off > 0; off >>= 1) s += __shfl_down_sync(0xffffffffu, s, off);
    if (lane == 0) sm[wid] = s;
    __syncthreads();
    if (tid == 0) {
        float t = 0.f;
#pragma unroll
        for (int i = 0; i < 8; i++) t += sm[i];
        stats[0] = t * (1.f / N);
    }
    __syncthreads();
    float mu = stats[0];

    float vs = 0.f;
#pragma unroll
    for (int i = 0; i < 4; i++) {
        float d = v[i] - mu;
        vs += d * d;
    }
#pragma unroll
    for (int off = 16; off > 0; off >>= 1) vs += __shfl_down_sync(0xffffffffu, vs, off);
    __syncthreads();
    if (lane == 0) sm[wid] = vs;
    __syncthreads();
    if (tid == 0) {
        float t = 0.f;
#pragma unroll
        for (int i = 0; i < 8; i++) t += sm[i];
        stats[1] = rsqrtf(t * (1.f / N) + LN_EPS);
    }
    __syncthreads();
    float rstd = stats[1];

#pragma unroll
    for (int i = 0; i < 4; i++) {
        int idx = tid + i * 256;
        Out[(size_t)row * N + idx] = (v[i] - mu) * rstd * G[idx] + Bt[idx];
    }
}

// ---------------------------------------------------------------------------
// Launch
// ---------------------------------------------------------------------------
extern "C" void kernel_launch(void* const* d_in, const int* in_sizes, int n_in,
                              void* d_out, int out_size)
{
    const float* x       = (const float*)d_in[0];
    const float* context = (const float*)d_in[1];
    const float* sa_wq = (const float*)d_in[2];
    const float* sa_wk = (const float*)d_in[3];
    const float* sa_wv = (const float*)d_in[4];
    const float* sa_wo = (const float*)d_in[5];
    const float* sa_bo = (const float*)d_in[6];
    const float* ca_wq = (const float*)d_in[7];
    const float* ca_wk = (const float*)d_in[8];
    const float* ca_wv = (const float*)d_in[9];
    const float* ca_wo = (const float*)d_in[10];
    const float* ca_bo = (const float*)d_in[11];
    const float* n1_g  = (const float*)d_in[12];
    const float* n1_b  = (const float*)d_in[13];
    const float* n2_g  = (const float*)d_in[14];
    const float* n2_b  = (const float*)d_in[15];
    const float* n3_g  = (const float*)d_in[16];
    const float* n3_b  = (const float*)d_in[17];
    const float* ff_w1 = (const float*)d_in[18];
    const float* ff_b1 = (const float*)d_in[19];
    const float* ff_w2 = (const float*)d_in[20];
    const float* ff_b2 = (const float*)d_in[21];
    float* out = (float*)d_out;

    float *q_, *k_, *v_, *attn_, *tmp_, *x1_, *x2_, *ff_;
    cudaGetSymbolAddress((void**)&q_,    g_q);
    cudaGetSymbolAddress((void**)&k_,    g_k);
    cudaGetSymbolAddress((void**)&v_,    g_v);
    cudaGetSymbolAddress((void**)&attn_, g_attn);
    cudaGetSymbolAddress((void**)&tmp_,  g_tmp);
    cudaGetSymbolAddress((void**)&x1_,   g_x1);
    cudaGetSymbolAddress((void**)&x2_,   g_x2);
    cudaGetSymbolAddress((void**)&ff_,   g_ff);

    dim3 gE(E / 128, M_ROWS / 128);      // N=1024 GEMMs
    dim3 gH(HID / 128, M_ROWS / 128);    // N=4096 GEMM
    dim3 gFA(BATCH * NH, T / FA_BR);

    // ---- Self-attention ----
    sgemm_kernel<<<gE, 256>>>(x, sa_wq, nullptr, q_, M_ROWS, E, E, 0);
    sgemm_kernel<<<gE, 256>>>(x, sa_wk, nullptr, k_, M_ROWS, E, E, 0);
    sgemm_kernel<<<gE, 256>>>(x, sa_wv, nullptr, v_, M_ROWS, E, E, 0);
    flash_attn_kernel<<<gFA, FA_BR>>>(q_, k_, v_, attn_, 1);
    sgemm_kernel<<<gE, 256>>>(attn_, sa_wo, sa_bo, tmp_, M_ROWS, E, E, 0);
    ln_residual_kernel<<<M_ROWS, 256>>>(x, tmp_, n1_g, n1_b, x1_);

    // ---- Cross-attention ----
    sgemm_kernel<<<gE, 256>>>(x1_,     ca_wq, nullptr, q_, M_ROWS, E, E, 0);
    sgemm_kernel<<<gE, 256>>>(context, ca_wk, nullptr, k_, M_ROWS, E, E, 0);
    sgemm_kernel<<<gE, 256>>>(context, ca_wv, nullptr, v_, M_ROWS, E, E, 0);
    flash_attn_kernel<<<gFA, FA_BR>>>(q_, k_, v_, attn_, 0);
    sgemm_kernel<<<gE, 256>>>(attn_, ca_wo, ca_bo, tmp_, M_ROWS, E, E, 0);
    ln_residual_kernel<<<M_ROWS, 256>>>(x1_, tmp_, n2_g, n2_b, x2_);

    // ---- FFN ----
    sgemm_kernel<<<gH, 256>>>(x2_, ff_w1, ff_b1, ff_, M_ROWS, HID, E, 1);
    sgemm_kernel<<<gE, 256>>>(ff_, ff_w2, ff_b2, tmp_, M_ROWS, E, HID, 0);
    ln_residual_kernel<<<M_ROWS, 256>>>(x2_, tmp_, n3_g, n3_b, out);
}

// round 3
// speedup vs baseline: 2.4260x; 2.4260x over previous
#include <cuda_runtime.h>
#include <cuda_fp16.h>
#include <math.h>
#include <stdint.h>

// Problem constants
#define BATCH 4
#define T 1024
#define E 1024
#define NH 16
#define HS 64
#define HID 4096
#define M_ROWS (BATCH * T)   // 4096
#define LN_EPS 1e-5f
#define ATT_SCALE 0.03125f   // E^-0.25 on q and k each -> E^-0.5 on dot

// ---------------------------------------------------------------------------
// Scratch (__device__ globals; no allocation allowed)
// ---------------------------------------------------------------------------
__device__ float  g_q[M_ROWS * E];
__device__ float  g_k[M_ROWS * E];
__device__ float  g_v[M_ROWS * E];
__device__ float  g_tmp[M_ROWS * E];
__device__ float  g_x1f[M_ROWS * E];
__device__ float  g_x2f[M_ROWS * E];
// split-A activation planes (hi/lo fp16)
__device__ __half g_xh[M_ROWS * E],   g_xl[M_ROWS * E];
__device__ __half g_ctxh[M_ROWS * E], g_ctxl[M_ROWS * E];
__device__ __half g_x1h[M_ROWS * E],  g_x1l[M_ROWS * E];
__device__ __half g_x2h[M_ROWS * E],  g_x2l[M_ROWS * E];
__device__ __half g_ath[M_ROWS * E],  g_atl[M_ROWS * E];
__device__ __half g_ffh[M_ROWS * HID], g_ffl[M_ROWS * HID];
// fp16 transposed weights [N,K]
__device__ __half g_sa_wqt[E * E], g_sa_wkt[E * E], g_sa_wvt[E * E], g_sa_wot[E * E];
__device__ __half g_ca_wqt[E * E], g_ca_wkt[E * E], g_ca_wvt[E * E], g_ca_wot[E * E];
__device__ __half g_w1t[HID * E], g_w2t[E * HID];

// ---------------------------------------------------------------------------
// PTX helpers (sm_80+-compatible: cp.async, ldmatrix, mma.sync)
// ---------------------------------------------------------------------------
__device__ __forceinline__ uint32_t smem_u32(const void* p) {
    uint32_t a;
    asm("{ .reg .u64 t; cvta.to.shared.u64 t, %1; cvt.u32.u64 %0, t; }"
        : "=r"(a) : "l"(p));
    return a;
}

#define CP_ASYNC16(saddr, gptr) \
    asm volatile("cp.async.cg.shared.global [%0], [%1], 16;" \
        :: "r"(saddr), "l"(gptr) : "memory")
#define CP_COMMIT()  asm volatile("cp.async.commit_group;" ::: "memory")
#define CP_WAIT0()   asm volatile("cp.async.wait_group 0;" ::: "memory")

#define LDSM4(r, addr) \
    asm volatile("ldmatrix.sync.aligned.m8n8.x4.shared.b16 {%0,%1,%2,%3}, [%4];" \
        : "=r"((r)[0]), "=r"((r)[1]), "=r"((r)[2]), "=r"((r)[3]) : "r"(addr))
#define LDSM2(r, addr) \
    asm volatile("ldmatrix.sync.aligned.m8n8.x2.shared.b16 {%0,%1}, [%2];" \
        : "=r"((r)[0]), "=r"((r)[1]) : "r"(addr))

__device__ __forceinline__ void mma16816(float* c, const uint32_t* a, const uint32_t* b) {
    asm volatile(
        "mma.sync.aligned.m16n8k16.row.col.f32.f16.f16.f32 "
        "{%0,%1,%2,%3}, {%4,%5,%6,%7}, {%8,%9}, {%0,%1,%2,%3};"
        : "+f"(c[0]), "+f"(c[1]), "+f"(c[2]), "+f"(c[3])
        : "r"(a[0]), "r"(a[1]), "r"(a[2]), "r"(a[3]), "r"(b[0]), "r"(b[1]));
}

// ---------------------------------------------------------------------------
// HGEMM with split-A: C[M,N] = (Ah+Al)[M,K] @ Bt[N,K]^T (+bias)(+relu)
// Output: fp32 C32  OR  hi/lo fp16 planes (Ch, Cl).
// Tile 128x128x64, 256 threads (8 warps, warp tile 64x32), 2-stage cp.async.
// ---------------------------------------------------------------------------
#define STAGE_BYTES 49152        // Ah 16K | Al 16K | B 16K
#define GSMEM_SZ    (2 * STAGE_BYTES)

__global__ void __launch_bounds__(256)
hgemm_kernel(const __half* __restrict__ Ah, const __half* __restrict__ Al,
             const __half* __restrict__ Bt, const float* __restrict__ bias,
             float* __restrict__ C32, __half* __restrict__ Ch, __half* __restrict__ Cl,
             int M, int N, int K, int relu)
{
    extern __shared__ char smem[];
    uint32_t sb = smem_u32(smem);
    int tid = threadIdx.x;
    int lane = tid & 31;
    int wid = tid >> 5;
    int wm = wid & 1;         // warp row (2)
    int wn = wid >> 1;        // warp col (4)
    int bx = blockIdx.x, by = blockIdx.y;

    const __half* gA = Ah + (size_t)by * 128 * K;
    const __half* gAl = Al + (size_t)by * 128 * K;
    const __half* gB = Bt + (size_t)bx * 128 * K;

    // cp.async layout: each thread loads 4 chunks of 16B per plane.
    int lrow = tid >> 3;       // 0..31
    int lch = tid & 7;         // 0..7
    uint32_t soff[4];
#pragma unroll
    for (int i = 0; i < 4; i++) {
        int r = lrow + 32 * i;
        soff[i] = (uint32_t)(r * 128 + ((lch ^ (r & 7)) * 16));
    }

    // fragment smem addressing (per mf/nf row offsets, swizzle keys)
    uint32_t aOff[4], aX[4], bOff[4], bX[4];
#pragma unroll
    for (int mf = 0; mf < 4; mf++) {
        int r = wm * 64 + mf * 16 + (lane & 15);
        aOff[mf] = r * 128; aX[mf] = r & 7;
    }
#pragma unroll
    for (int nf = 0; nf < 4; nf++) {
        int r = wn * 32 + nf * 8 + (lane & 7);
        bOff[nf] = r * 128; bX[nf] = r & 7;
    }
    int aSel = lane >> 4;          // 0/1
    int bSel = (lane >> 3) & 1;    // 0/1

    float acc[4][4][4];
#pragma unroll
    for (int mf = 0; mf < 4; mf++)
#pragma unroll
        for (int nf = 0; nf < 4; nf++)
#pragma unroll
            for (int r = 0; r < 4; r++) acc[mf][nf][r] = 0.f;

    const int KT = K >> 6;   // K/64

    // prologue: stage 0
    {
        uint32_t st = sb;
#pragma unroll
        for (int i = 0; i < 4; i++) {
            int r = lrow + 32 * i;
            const __half* pa = gA + (size_t)r * K + lch * 8;
            const __half* pl = gAl + (size_t)r * K + lch * 8;
            const __half* pb = gB + (size_t)r * K + lch * 8;
            CP_ASYNC16(st + soff[i], pa);
            CP_ASYNC16(st + 16384 + soff[i], pl);
            CP_ASYNC16(st + 32768 + soff[i], pb);
        }
        CP_COMMIT();
    }

    for (int kt = 0; kt < KT; kt++) {
        CP_WAIT0();
        __syncthreads();

        if (kt + 1 < KT) {
            uint32_t st = sb + ((kt + 1) & 1) * STAGE_BYTES;
            int k0 = (kt + 1) << 6;
#pragma unroll
            for (int i = 0; i < 4; i++) {
                int r = lrow + 32 * i;
                const __half* pa = gA + (size_t)r * K + k0 + lch * 8;
                const __half* pl = gAl + (size_t)r * K + k0 + lch * 8;
                const __half* pb = gB + (size_t)r * K + k0 + lch * 8;
                CP_ASYNC16(st + soff[i], pa);
                CP_ASYNC16(st + 16384 + soff[i], pl);
                CP_ASYNC16(st + 32768 + soff[i], pb);
            }
            CP_COMMIT();
        }

        uint32_t aBase = sb + (kt & 1) * STAGE_BYTES;
        uint32_t lBase = aBase + 16384;
        uint32_t bBase = aBase + 32768;

#pragma unroll
        for (int ks = 0; ks < 4; ks++) {
            int cA = ks * 2 + aSel;
            int cB = ks * 2 + bSel;
            uint32_t a[4][4], b[4][2];
#pragma unroll
            for (int mf = 0; mf < 4; mf++)
                LDSM4(a[mf], aBase + aOff[mf] + ((cA ^ aX[mf]) << 4));
#pragma unroll
            for (int nf = 0; nf < 4; nf++)
                LDSM2(b[nf], bBase + bOff[nf] + ((cB ^ bX[nf]) << 4));
#pragma unroll
            for (int mf = 0; mf < 4; mf++)
#pragma unroll
                for (int nf = 0; nf < 4; nf++)
                    mma16816(acc[mf][nf], a[mf], b[nf]);
            // lo-plane correction (reuses B fragments)
            uint32_t al[4][4];
#pragma unroll
            for (int mf = 0; mf < 4; mf++)
                LDSM4(al[mf], lBase + aOff[mf] + ((cA ^ aX[mf]) << 4));
#pragma unroll
            for (int mf = 0; mf < 4; mf++)
#pragma unroll
                for (int nf = 0; nf < 4; nf++)
                    mma16816(acc[mf][nf], al[mf], b[nf]);
        }
        __syncthreads();
    }

    // Epilogue
    int g = lane >> 2, tig = lane & 3;
#pragma unroll
    for (int mf = 0; mf < 4; mf++) {
#pragma unroll
        for (int nf = 0; nf < 4; nf++) {
            int r0 = by * 128 + wm * 64 + mf * 16 + g;
            int c0 = bx * 128 + wn * 32 + nf * 8 + tig * 2;
            float b0 = 0.f, b1 = 0.f;
            if (bias) { b0 = bias[c0]; b1 = bias[c0 + 1]; }
            float v0 = acc[mf][nf][0] + b0, v1 = acc[mf][nf][1] + b1;
            float v2 = acc[mf][nf][2] + b0, v3 = acc[mf][nf][3] + b1;
            if (relu) {
                v0 = fmaxf(v0, 0.f); v1 = fmaxf(v1, 0.f);
                v2 = fmaxf(v2, 0.f); v3 = fmaxf(v3, 0.f);
            }
            if (C32) {
                *(float2*)(C32 + (size_t)r0 * N + c0) = make_float2(v0, v1);
                *(float2*)(C32 + (size_t)(r0 + 8) * N + c0) = make_float2(v2, v3);
            } else {
                __half h0 = __float2half(v0), h1 = __float2half(v1);
                __half h2 = __float2half(v2), h3 = __float2half(v3);
                *(__half2*)(Ch + (size_t)r0 * N + c0) = __halves2half2(h0, h1);
                *(__half2*)(Ch + (size_t)(r0 + 8) * N + c0) = __halves2half2(h2, h3);
                __half l0 = __float2half(v0 - __half2float(h0));
                __half l1 = __float2half(v1 - __half2float(h1));
                __half l2 = __float2half(v2 - __half2float(h2));
                __half l3 = __float2half(v3 - __half2float(h3));
                *(__half2*)(Cl + (size_t)r0 * N + c0) = __halves2half2(l0, l1);
                *(__half2*)(Cl + (size_t)(r0 + 8) * N + c0) = __halves2half2(l2, l3);
            }
        }
    }
}

// ---------------------------------------------------------------------------
// Weight transpose to fp16: out[C][R] = fp16(in[R][C])
// ---------------------------------------------------------------------------
__global__ void __launch_bounds__(256)
transpose_h_kernel(const float* __restrict__ in, __half* __restrict__ out,
                   int R, int C)
{
    __shared__ float t[32][33];
    int bx = blockIdx.x * 32, by = blockIdx.y * 32;
    int x = threadIdx.x, y = threadIdx.y;
#pragma unroll
    for (int j = 0; j < 32; j += 8)
        t[y + j][x] = in[(size_t)(by + y + j) * C + bx + x];
    __syncthreads();
#pragma unroll
    for (int j = 0; j < 32; j += 8)
        out[(size_t)(bx + y + j) * R + by + x] = __float2half(t[x][y + j]);
}

// ---------------------------------------------------------------------------
// fp32 -> hi/lo fp16 planes
// ---------------------------------------------------------------------------
__global__ void __launch_bounds__(256)
split_h_kernel(const float* __restrict__ in, __half* __restrict__ hi,
               __half* __restrict__ lo, int n)
{
    int i = blockIdx.x * 256 + threadIdx.x;
    if (i < n) {
        float v = in[i];
        __half h = __float2half(v);
        hi[i] = h;
        lo[i] = __float2half(v - __half2float(h));
    }
}

// ---------------------------------------------------------------------------
// Flash attention (fp32, online softmax, __expf). Writes hi/lo fp16 output.
// ---------------------------------------------------------------------------
#define FA_BR 128
#define FA_BC 64

__global__ void __launch_bounds__(FA_BR)
flash_attn_kernel(const float* __restrict__ Q, const float* __restrict__ Km,
                  const float* __restrict__ Vm, __half* __restrict__ Oh,
                  __half* __restrict__ Ol, int causal)
{
    __shared__ float smem[2 * FA_BC * HS];
    float* Ks = smem;
    float* Vs = smem + FA_BC * HS;

    int bh = blockIdx.x;
    int b = bh >> 4;
    int h = bh & 15;
    int qtile = blockIdx.y;
    int tid = threadIdx.x;
    int qi = qtile * FA_BR + tid;

    float q[HS];
    {
        const float* Qg = Q + ((size_t)(b * T + qtile * FA_BR)) * E + h * HS;
        for (int i = tid; i < FA_BR * HS / 4; i += FA_BR) {
            int r = i >> 4;
            int c = i & 15;
            ((float4*)smem)[(size_t)r * 16 + c] = *(const float4*)(Qg + (size_t)r * E + c * 4);
        }
        __syncthreads();
#pragma unroll
        for (int d = 0; d < HS; d++) q[d] = smem[tid * HS + d];
        __syncthreads();
    }

    float o[HS];
#pragma unroll
    for (int d = 0; d < HS; d++) o[d] = 0.f;
    float m = -1e30f, l = 0.f;

    int ktiles = causal ? 2 * (qtile + 1) : (T / FA_BC);

    for (int kt = 0; kt < ktiles; kt++) {
        const float* Kg = Km + ((size_t)(b * T + kt * FA_BC)) * E + h * HS;
        const float* Vg = Vm + ((size_t)(b * T + kt * FA_BC)) * E + h * HS;
        for (int i = tid; i < FA_BC * HS / 4; i += FA_BR) {
            int r = i >> 4;
            int c = i & 15;
            ((float4*)Ks)[i] = *(const float4*)(Kg + (size_t)r * E + c * 4);
            ((float4*)Vs)[i] = *(const float4*)(Vg + (size_t)r * E + c * 4);
        }
        __syncthreads();

        int jmax = FA_BC;
        if (causal) {
            int rel = qi - kt * FA_BC;
            jmax = rel + 1;
            if (jmax > FA_BC) jmax = FA_BC;
            if (jmax < 0) jmax = 0;
        }

#pragma unroll 2
        for (int j = 0; j < jmax; j++) {
            const float4* kr = (const float4*)(Ks + j * HS);
            float s = 0.f;
#pragma unroll
            for (int d = 0; d < 16; d++) {
                float4 kv = kr[d];
                s += q[4 * d + 0] * kv.x + q[4 * d + 1] * kv.y
                   + q[4 * d + 2] * kv.z + q[4 * d + 3] * kv.w;
            }
            s *= ATT_SCALE;
            if (s > m) {
                float alpha = __expf(m - s);   // exp(-inf)=0 handles first iter
                l *= alpha;
#pragma unroll
                for (int d = 0; d < HS; d++) o[d] *= alpha;
                m = s;
            }
            float p = __expf(s - m);
            l += p;
            const float4* vr = (const float4*)(Vs + j * HS);
#pragma unroll
            for (int d = 0; d < 16; d++) {
                float4 vv = vr[d];
                o[4 * d + 0] += p * vv.x;
                o[4 * d + 1] += p * vv.y;
                o[4 * d + 2] += p * vv.z;
                o[4 * d + 3] += p * vv.w;
            }
        }
        __syncthreads();
    }

    float inv = 1.f / l;
    size_t base = ((size_t)(b * T + qi)) * E + h * HS;
#pragma unroll
    for (int d = 0; d < HS; d += 2) {
        float v0 = o[d] * inv, v1 = o[d + 1] * inv;
        __half h0 = __float2half(v0), h1 = __float2half(v1);
        *(__half2*)(Oh + base + d) = __halves2half2(h0, h1);
        __half l0 = __float2half(v0 - __half2float(h0));
        __half l1 = __float2half(v1 - __half2float(h1));
        *(__half2*)(Ol + base + d) = __halves2half2(l0, l1);
    }
}

// ---------------------------------------------------------------------------
// Fused residual + LayerNorm: out = LN(x + r) * g + b  (+ optional hi/lo planes)
// ---------------------------------------------------------------------------
__global__ void __launch_bounds__(256)
ln_residual_kernel(const float* __restrict__ X, const float* __restrict__ R,
                   const float* __restrict__ G, const float* __restrict__ Bt,
                   float* __restrict__ Out, __half* __restrict__ Oh,
                   __half* __restrict__ Ol)
{
    const int N = E;
    int row = blockIdx.x;
    int tid = threadIdx.x;
    int lane = tid & 31, wid = tid >> 5;
    __shared__ float sm[8];
    __shared__ float stats[2];

    float v[4];
    float s = 0.f;
#pragma unroll
    for (int i = 0; i < 4; i++) {
        int idx = tid + i * 256;
        v[i] = X[(size_t)row * N + idx] + R[(size_t)row * N + idx];
        s += v[i];
    }
#pragma unroll
    for (int off = 16; off > 0; off >>= 1) s += __shfl_down_sync(0xffffffffu, s, off);
    if (lane == 0) sm[wid] = s;
    __syncthreads();
    if (tid == 0) {
        float t = 0.f;
#pragma unroll
        for (int i = 0; i < 8; i++) t += sm[i];
        stats[0] = t * (1.f / N);
    }
    __syncthreads();
    float mu = stats[0];

    float vs = 0.f;
#pragma unroll
    for (int i = 0; i < 4; i++) {
        float d = v[i] - mu;
        vs += d * d;
    }
#pragma unroll
    for (int off = 16; off > 0; off >>= 1) vs += __shfl_down_sync(0xffffffffu, vs, off);
    __syncthreads();
    if (lane == 0) sm[wid] = vs;
    __syncthreads();
    if (tid == 0) {
        float t = 0.f;
#pragma unroll
        for (int i = 0; i < 8; i++) t += sm[i];
        stats[1] = rsqrtf(t * (1.f / N) + LN_EPS);
    }
    __syncthreads();
    float rstd = stats[1];

#pragma unroll
    for (int i = 0; i < 4; i++) {
        int idx = tid + i * 256;
        float y = (v[i] - mu) * rstd * G[idx] + Bt[idx];
        Out[(size_t)row * N + idx] = y;
        if (Oh) {
            __half hh = __float2half(y);
            Oh[(size_t)row * N + idx] = hh;
            Ol[(size_t)row * N + idx] = __float2half(y - __half2float(hh));
        }
    }
}

// ---------------------------------------------------------------------------
// Launch
// ---------------------------------------------------------------------------
extern "C" void kernel_launch(void* const* d_in, const int* in_sizes, int n_in,
                              void* d_out, int out_size)
{
    const float* x       = (const float*)d_in[0];
    const float* context = (const float*)d_in[1];
    const float* sa_wq = (const float*)d_in[2];
    const float* sa_wk = (const float*)d_in[3];
    const float* sa_wv = (const float*)d_in[4];
    const float* sa_wo = (const float*)d_in[5];
    const float* sa_bo = (const float*)d_in[6];
    const float* ca_wq = (const float*)d_in[7];
    const float* ca_wk = (const float*)d_in[8];
    const float* ca_wv = (const float*)d_in[9];
    const float* ca_wo = (const float*)d_in[10];
    const float* ca_bo = (const float*)d_in[11];
    const float* n1_g  = (const float*)d_in[12];
    const float* n1_b  = (const float*)d_in[13];
    const float* n2_g  = (const float*)d_in[14];
    const float* n2_b  = (const float*)d_in[15];
    const float* n3_g  = (const float*)d_in[16];
    const float* n3_b  = (const float*)d_in[17];
    const float* ff_w1 = (const float*)d_in[18];
    const float* ff_b1 = (const float*)d_in[19];
    const float* ff_w2 = (const float*)d_in[20];
    const float* ff_b2 = (const float*)d_in[21];
    float* out = (float*)d_out;

    float *q_, *k_, *v_, *tmp_, *x1f_, *x2f_;
    cudaGetSymbolAddress((void**)&q_,   g_q);
    cudaGetSymbolAddress((void**)&k_,   g_k);
    cudaGetSymbolAddress((void**)&v_,   g_v);
    cudaGetSymbolAddress((void**)&tmp_, g_tmp);
    cudaGetSymbolAddress((void**)&x1f_, g_x1f);
    cudaGetSymbolAddress((void**)&x2f_, g_x2f);

    __half *xh, *xl, *ctxh, *ctxl, *x1h, *x1l, *x2h, *x2l, *ath, *atl, *ffh, *ffl;
    cudaGetSymbolAddress((void**)&xh,   g_xh);   cudaGetSymbolAddress((void**)&xl,   g_xl);
    cudaGetSymbolAddress((void**)&ctxh, g_ctxh); cudaGetSymbolAddress((void**)&ctxl, g_ctxl);
    cudaGetSymbolAddress((void**)&x1h,  g_x1h);  cudaGetSymbolAddress((void**)&x1l,  g_x1l);
    cudaGetSymbolAddress((void**)&x2h,  g_x2h);  cudaGetSymbolAddress((void**)&x2l,  g_x2l);
    cudaGetSymbolAddress((void**)&ath,  g_ath);  cudaGetSymbolAddress((void**)&atl,  g_atl);
    cudaGetSymbolAddress((void**)&ffh,  g_ffh);  cudaGetSymbolAddress((void**)&ffl,  g_ffl);

    __half *wqt, *wkt, *wvt, *wot, *cwqt, *cwkt, *cwvt, *cwot, *w1t, *w2t;
    cudaGetSymbolAddress((void**)&wqt,  g_sa_wqt); cudaGetSymbolAddress((void**)&wkt,  g_sa_wkt);
    cudaGetSymbolAddress((void**)&wvt,  g_sa_wvt); cudaGetSymbolAddress((void**)&wot,  g_sa_wot);
    cudaGetSymbolAddress((void**)&cwqt, g_ca_wqt); cudaGetSymbolAddress((void**)&cwkt, g_ca_wkt);
    cudaGetSymbolAddress((void**)&cwvt, g_ca_wvt); cudaGetSymbolAddress((void**)&cwot, g_ca_wot);
    cudaGetSymbolAddress((void**)&w1t,  g_w1t);    cudaGetSymbolAddress((void**)&w2t,  g_w2t);

    cudaFuncSetAttribute(hgemm_kernel,
                         cudaFuncAttributeMaxDynamicSharedMemorySize, GSMEM_SZ);

    dim3 tB(32, 8);
    dim3 tGee(E / 32, E / 32);
    dim3 tG1(HID / 32, E / 32);
    dim3 tG2(E / 32, HID / 32);
    transpose_h_kernel<<<tGee, tB>>>(sa_wq, wqt, E, E);
    transpose_h_kernel<<<tGee, tB>>>(sa_wk, wkt, E, E);
    transpose_h_kernel<<<tGee, tB>>>(sa_wv, wvt, E, E);
    transpose_h_kernel<<<tGee, tB>>>(sa_wo, wot, E, E);
    transpose_h_kernel<<<tGee, tB>>>(ca_wq, cwqt, E, E);
    transpose_h_kernel<<<tGee, tB>>>(ca_wk, cwkt, E, E);
    transpose_h_kernel<<<tGee, tB>>>(ca_wv, cwvt, E, E);
    transpose_h_kernel<<<tGee, tB>>>(ca_wo, cwot, E, E);
    transpose_h_kernel<<<tG1, tB>>>(ff_w1, w1t, E, HID);
    transpose_h_kernel<<<tG2, tB>>>(ff_w2, w2t, HID, E);

    int nElem = M_ROWS * E;
    split_h_kernel<<<nElem / 256, 256>>>(x, xh, xl, nElem);
    split_h_kernel<<<nElem / 256, 256>>>(context, ctxh, ctxl, nElem);

    dim3 gE(E / 128, M_ROWS / 128);
    dim3 gH(HID / 128, M_ROWS / 128);
    dim3 gFA(BATCH * NH, T / FA_BR);

    // ---- Self-attention ----
    hgemm_kernel<<<gE, 256, GSMEM_SZ>>>(xh, xl, wqt, nullptr, q_, nullptr, nullptr, M_ROWS, E, E, 0);
    hgemm_kernel<<<gE, 256, GSMEM_SZ>>>(xh, xl, wkt, nullptr, k_, nullptr, nullptr, M_ROWS, E, E, 0);
    hgemm_kernel<<<gE, 256, GSMEM_SZ>>>(xh, xl, wvt, nullptr, v_, nullptr, nullptr, M_ROWS, E, E, 0);
    flash_attn_kernel<<<gFA, FA_BR>>>(q_, k_, v_, ath, atl, 1);
    hgemm_kernel<<<gE, 256, GSMEM_SZ>>>(ath, atl, wot, sa_bo, tmp_, nullptr, nullptr, M_ROWS, E, E, 0);
    ln_residual_kernel<<<M_ROWS, 256>>>(x, tmp_, n1_g, n1_b, x1f_, x1h, x1l);

    // ---- Cross-attention ----
    hgemm_kernel<<<gE, 256, GSMEM_SZ>>>(x1h, x1l, cwqt, nullptr, q_, nullptr, nullptr, M_ROWS, E, E, 0);
    hgemm_kernel<<<gE, 256, GSMEM_SZ>>>(ctxh, ctxl, cwkt, nullptr, k_, nullptr, nullptr, M_ROWS, E, E, 0);
    hgemm_kernel<<<gE, 256, GSMEM_SZ>>>(ctxh, ctxl, cwvt, nullptr, v_, nullptr, nullptr, M_ROWS, E, E, 0);
    flash_attn_kernel<<<gFA, FA_BR>>>(q_, k_, v_, ath, atl, 0);
    hgemm_kernel<<<gE, 256, GSMEM_SZ>>>(ath, atl, cwot, ca_bo, tmp_, nullptr, nullptr, M_ROWS, E, E, 0);
    ln_residual_kernel<<<M_ROWS, 256>>>(x1f_, tmp_, n2_g, n2_b, x2f_, x2h, x2l);

    // ---- FFN ----
    hgemm_kernel<<<gH, 256, GSMEM_SZ>>>(x2h, x2l, w1t, ff_b1, nullptr, ffh, ffl, M_ROWS, HID, E, 1);
    hgemm_kernel<<<gE, 256, GSMEM_SZ>>>(ffh, ffl, w2t, ff_b2, tmp_, nullptr, nullptr, M_ROWS, E, HID, 0);
    ln_residual_kernel<<<M_ROWS, 256>>>(x2f_, tmp_, n3_g, n3_b, out, nullptr, nullptr);
}

// round 4
// speedup vs baseline: 5.6661x; 2.3355x over previous
#include <cuda_runtime.h>
#include <cuda_fp16.h>
#include <math.h>
#include <stdint.h>

// Problem constants
#define BATCH 4
#define T 1024
#define E 1024
#define NH 16
#define HS 64
#define HID 4096
#define M_ROWS (BATCH * T)   // 4096
#define LN_EPS 1e-5f
#define ATT_SCALE 0.03125f   // E^-0.25 on q and k each -> E^-0.5 on dot

// ---------------------------------------------------------------------------
// Scratch (__device__ globals; no allocation allowed)
// ---------------------------------------------------------------------------
__device__ float  g_tmp[M_ROWS * E];
__device__ float  g_x1f[M_ROWS * E];
__device__ float  g_x2f[M_ROWS * E];
// fp16 q/k/v for tensor-core attention
__device__ __half g_qh[M_ROWS * E], g_kh[M_ROWS * E], g_vh[M_ROWS * E];
// split-A activation planes (hi/lo fp16)
__device__ __half g_xh[M_ROWS * E],   g_xl[M_ROWS * E];
__device__ __half g_ctxh[M_ROWS * E], g_ctxl[M_ROWS * E];
__device__ __half g_x1h[M_ROWS * E],  g_x1l[M_ROWS * E];
__device__ __half g_x2h[M_ROWS * E],  g_x2l[M_ROWS * E];
__device__ __half g_ath[M_ROWS * E],  g_atl[M_ROWS * E];
__device__ __half g_ffh[M_ROWS * HID], g_ffl[M_ROWS * HID];
// fp16 transposed weights [N,K]
__device__ __half g_sa_wqt[E * E], g_sa_wkt[E * E], g_sa_wvt[E * E], g_sa_wot[E * E];
__device__ __half g_ca_wqt[E * E], g_ca_wkt[E * E], g_ca_wvt[E * E], g_ca_wot[E * E];
__device__ __half g_w1t[HID * E], g_w2t[E * HID];

// ---------------------------------------------------------------------------
// PTX helpers (sm_80+-compatible: cp.async, ldmatrix, mma.sync)
// ---------------------------------------------------------------------------
__device__ __forceinline__ uint32_t smem_u32(const void* p) {
    uint32_t a;
    asm("{ .reg .u64 t; cvta.to.shared.u64 t, %1; cvt.u32.u64 %0, t; }"
        : "=r"(a) : "l"(p));
    return a;
}

#define CP_ASYNC16(saddr, gptr) \
    asm volatile("cp.async.cg.shared.global [%0], [%1], 16;" \
        :: "r"(saddr), "l"(gptr) : "memory")
#define CP_COMMIT()  asm volatile("cp.async.commit_group;" ::: "memory")
#define CP_WAIT0()   asm volatile("cp.async.wait_group 0;" ::: "memory")

#define LDSM4(r, addr) \
    asm volatile("ldmatrix.sync.aligned.m8n8.x4.shared.b16 {%0,%1,%2,%3}, [%4];" \
        : "=r"((r)[0]), "=r"((r)[1]), "=r"((r)[2]), "=r"((r)[3]) : "r"(addr))
#define LDSM2(r, addr) \
    asm volatile("ldmatrix.sync.aligned.m8n8.x2.shared.b16 {%0,%1}, [%2];" \
        : "=r"((r)[0]), "=r"((r)[1]) : "r"(addr))
#define LDSM4T(r, addr) \
    asm volatile("ldmatrix.sync.aligned.m8n8.x4.trans.shared.b16 {%0,%1,%2,%3}, [%4];" \
        : "=r"((r)[0]), "=r"((r)[1]), "=r"((r)[2]), "=r"((r)[3]) : "r"(addr))

__device__ __forceinline__ void mma16816(float* c, const uint32_t* a, const uint32_t* b) {
    asm volatile(
        "mma.sync.aligned.m16n8k16.row.col.f32.f16.f16.f32 "
        "{%0,%1,%2,%3}, {%4,%5,%6,%7}, {%8,%9}, {%0,%1,%2,%3};"
        : "+f"(c[0]), "+f"(c[1]), "+f"(c[2]), "+f"(c[3])
        : "r"(a[0]), "r"(a[1]), "r"(a[2]), "r"(a[3]), "r"(b[0]), "r"(b[1]));
}

// ---------------------------------------------------------------------------
// HGEMM with split-A: C[M,N] = (Ah+Al)[M,K] @ Bt[N,K]^T (+bias)(+relu)
// Output modes: fp32 C32 | hi/lo fp16 (Ch,Cl) | hi-only fp16 (Ch).
// Tile 128x128x64, 256 threads (8 warps, warp tile 64x32), 2-stage cp.async.
// ---------------------------------------------------------------------------
#define STAGE_BYTES 49152        // Ah 16K | Al 16K | B 16K
#define GSMEM_SZ    (2 * STAGE_BYTES)

__global__ void __launch_bounds__(256)
hgemm_kernel(const __half* __restrict__ Ah, const __half* __restrict__ Al,
             const __half* __restrict__ Bt, const float* __restrict__ bias,
             float* __restrict__ C32, __half* __restrict__ Ch, __half* __restrict__ Cl,
             int M, int N, int K, int relu)
{
    extern __shared__ char smem[];
    uint32_t sb = smem_u32(smem);
    int tid = threadIdx.x;
    int lane = tid & 31;
    int wid = tid >> 5;
    int wm = wid & 1;         // warp row (2)
    int wn = wid >> 1;        // warp col (4)
    int bx = blockIdx.x, by = blockIdx.y;

    const __half* gA = Ah + (size_t)by * 128 * K;
    const __half* gAl = Al + (size_t)by * 128 * K;
    const __half* gB = Bt + (size_t)bx * 128 * K;

    int lrow = tid >> 3;       // 0..31
    int lch = tid & 7;         // 0..7
    uint32_t soff[4];
#pragma unroll
    for (int i = 0; i < 4; i++) {
        int r = lrow + 32 * i;
        soff[i] = (uint32_t)(r * 128 + ((lch ^ (r & 7)) * 16));
    }

    uint32_t aOff[4], aX[4], bOff[4], bX[4];
#pragma unroll
    for (int mf = 0; mf < 4; mf++) {
        int r = wm * 64 + mf * 16 + (lane & 15);
        aOff[mf] = r * 128; aX[mf] = r & 7;
    }
#pragma unroll
    for (int nf = 0; nf < 4; nf++) {
        int r = wn * 32 + nf * 8 + (lane & 7);
        bOff[nf] = r * 128; bX[nf] = r & 7;
    }
    int aSel = lane >> 4;          // 0/1
    int bSel = (lane >> 3) & 1;    // 0/1

    float acc[4][4][4];
#pragma unroll
    for (int mf = 0; mf < 4; mf++)
#pragma unroll
        for (int nf = 0; nf < 4; nf++)
#pragma unroll
            for (int r = 0; r < 4; r++) acc[mf][nf][r] = 0.f;

    const int KT = K >> 6;   // K/64

    {
        uint32_t st = sb;
#pragma unroll
        for (int i = 0; i < 4; i++) {
            int r = lrow + 32 * i;
            CP_ASYNC16(st + soff[i],         gA  + (size_t)r * K + lch * 8);
            CP_ASYNC16(st + 16384 + soff[i], gAl + (size_t)r * K + lch * 8);
            CP_ASYNC16(st + 32768 + soff[i], gB  + (size_t)r * K + lch * 8);
        }
        CP_COMMIT();
    }

    for (int kt = 0; kt < KT; kt++) {
        CP_WAIT0();
        __syncthreads();

        if (kt + 1 < KT) {
            uint32_t st = sb + ((kt + 1) & 1) * STAGE_BYTES;
            int k0 = (kt + 1) << 6;
#pragma unroll
            for (int i = 0; i < 4; i++) {
                int r = lrow + 32 * i;
                CP_ASYNC16(st + soff[i],         gA  + (size_t)r * K + k0 + lch * 8);
                CP_ASYNC16(st + 16384 + soff[i], gAl + (size_t)r * K + k0 + lch * 8);
                CP_ASYNC16(st + 32768 + soff[i], gB  + (size_t)r * K + k0 + lch * 8);
            }
            CP_COMMIT();
        }

        uint32_t aBase = sb + (kt & 1) * STAGE_BYTES;
        uint32_t lBase = aBase + 16384;
        uint32_t bBase = aBase + 32768;

#pragma unroll
        for (int ks = 0; ks < 4; ks++) {
            int cA = ks * 2 + aSel;
            int cB = ks * 2 + bSel;
            uint32_t a[4][4], b[4][2];
#pragma unroll
            for (int mf = 0; mf < 4; mf++)
                LDSM4(a[mf], aBase + aOff[mf] + ((cA ^ aX[mf]) << 4));
#pragma unroll
            for (int nf = 0; nf < 4; nf++)
                LDSM2(b[nf], bBase + bOff[nf] + ((cB ^ bX[nf]) << 4));
#pragma unroll
            for (int mf = 0; mf < 4; mf++)
#pragma unroll
                for (int nf = 0; nf < 4; nf++)
                    mma16816(acc[mf][nf], a[mf], b[nf]);
            uint32_t al[4][4];
#pragma unroll
            for (int mf = 0; mf < 4; mf++)
                LDSM4(al[mf], lBase + aOff[mf] + ((cA ^ aX[mf]) << 4));
#pragma unroll
            for (int mf = 0; mf < 4; mf++)
#pragma unroll
                for (int nf = 0; nf < 4; nf++)
                    mma16816(acc[mf][nf], al[mf], b[nf]);
        }
        __syncthreads();
    }

    int g = lane >> 2, tig = lane & 3;
#pragma unroll
    for (int mf = 0; mf < 4; mf++) {
#pragma unroll
        for (int nf = 0; nf < 4; nf++) {
            int r0 = by * 128 + wm * 64 + mf * 16 + g;
            int c0 = bx * 128 + wn * 32 + nf * 8 + tig * 2;
            float b0 = 0.f, b1 = 0.f;
            if (bias) { b0 = bias[c0]; b1 = bias[c0 + 1]; }
            float v0 = acc[mf][nf][0] + b0, v1 = acc[mf][nf][1] + b1;
            float v2 = acc[mf][nf][2] + b0, v3 = acc[mf][nf][3] + b1;
            if (relu) {
                v0 = fmaxf(v0, 0.f); v1 = fmaxf(v1, 0.f);
                v2 = fmaxf(v2, 0.f); v3 = fmaxf(v3, 0.f);
            }
            if (C32) {
                *(float2*)(C32 + (size_t)r0 * N + c0) = make_float2(v0, v1);
                *(float2*)(C32 + (size_t)(r0 + 8) * N + c0) = make_float2(v2, v3);
            } else {
                __half h0 = __float2half(v0), h1 = __float2half(v1);
                __half h2 = __float2half(v2), h3 = __float2half(v3);
                *(__half2*)(Ch + (size_t)r0 * N + c0) = __halves2half2(h0, h1);
                *(__half2*)(Ch + (size_t)(r0 + 8) * N + c0) = __halves2half2(h2, h3);
                if (Cl) {
                    __half l0 = __float2half(v0 - __half2float(h0));
                    __half l1 = __float2half(v1 - __half2float(h1));
                    __half l2 = __float2half(v2 - __half2float(h2));
                    __half l3 = __float2half(v3 - __half2float(h3));
                    *(__half2*)(Cl + (size_t)r0 * N + c0) = __halves2half2(l0, l1);
                    *(__half2*)(Cl + (size_t)(r0 + 8) * N + c0) = __halves2half2(l2, l3);
                }
            }
        }
    }
}

// ---------------------------------------------------------------------------
// Tensor-core flash attention.
// grid (BATCH*NH, T/64), 128 threads (4 warps x 16 q-rows). BC=64.
// fp16 Q/K/V in, online softmax fp32, output hi/lo fp16 planes.
// ---------------------------------------------------------------------------
__global__ void __launch_bounds__(128)
fa_mma_kernel(const __half* __restrict__ Qm, const __half* __restrict__ Km,
              const __half* __restrict__ Vm, __half* __restrict__ Oh,
              __half* __restrict__ Ol, int causal)
{
    __shared__ __half sQ[64 * 64];
    __shared__ __half sK[2][64 * 64];
    __shared__ __half sV[2][64 * 64];

    int tid = threadIdx.x, lane = tid & 31, w = tid >> 5;
    int g = lane >> 2, tig = lane & 3;
    int bh = blockIdx.x, b = bh >> 4, h = bh & 15;
    int qt = blockIdx.y;

    uint32_t sq = smem_u32(sQ);
    uint32_t skb[2] = { smem_u32(sK[0]), smem_u32(sK[1]) };
    uint32_t svb[2] = { smem_u32(sV[0]), smem_u32(sV[1]) };

    const __half* Qg = Qm + ((size_t)(b * T + qt * 64)) * E + h * HS;
    const __half* K0 = Km + ((size_t)(b * T)) * E + h * HS;
    const __half* V0 = Vm + ((size_t)(b * T)) * E + h * HS;

    // Stage Q + K/V tile 0 (one cp.async group)
#pragma unroll
    for (int i = 0; i < 4; i++) {
        int c = tid + i * 128; int r = c >> 3; int ch = c & 7;
        uint32_t off = r * 128 + ((ch ^ (r & 7)) << 4);
        CP_ASYNC16(sq + off, Qg + (size_t)r * E + ch * 8);
        CP_ASYNC16(skb[0] + off, K0 + (size_t)r * E + ch * 8);
        CP_ASYNC16(svb[0] + off, V0 + (size_t)r * E + ch * 8);
    }
    CP_COMMIT();
    CP_WAIT0();
    __syncthreads();

    // Q fragments (16 rows per warp, 4 k16-steps)
    uint32_t qf[4][4];
    {
        int r = w * 16 + (lane & 15); int sel = lane >> 4; int rx = r & 7;
        uint32_t ro = sq + r * 128;
#pragma unroll
        for (int ks = 0; ks < 4; ks++)
            LDSM4(qf[ks], ro + (((2 * ks + sel) ^ rx) << 4));
    }

    float oacc[8][4];
#pragma unroll
    for (int n = 0; n < 8; n++)
#pragma unroll
        for (int e = 0; e < 4; e++) oacc[n][e] = 0.f;
    float m0 = -1e30f, m1 = -1e30f, l0 = 0.f, l1 = 0.f;

    int nk = causal ? (qt + 1) : (T / 64);

    for (int kt = 0; kt < nk; kt++) {
        int cur = kt & 1;
        if (kt + 1 < nk) {
            int nst = cur ^ 1;
            const __half* Kg = Km + ((size_t)(b * T + (kt + 1) * 64)) * E + h * HS;
            const __half* Vg = Vm + ((size_t)(b * T + (kt + 1) * 64)) * E + h * HS;
#pragma unroll
            for (int i = 0; i < 4; i++) {
                int c = tid + i * 128; int r = c >> 3; int ch = c & 7;
                uint32_t off = r * 128 + ((ch ^ (r & 7)) << 4);
                CP_ASYNC16(skb[nst] + off, Kg + (size_t)r * E + ch * 8);
                CP_ASYNC16(svb[nst] + off, Vg + (size_t)r * E + ch * 8);
            }
            CP_COMMIT();
        }

        // S = Q @ K^T  (16 x 64 per warp)
        float sacc[8][4];
#pragma unroll
        for (int n = 0; n < 8; n++)
#pragma unroll
            for (int e = 0; e < 4; e++) sacc[n][e] = 0.f;

        uint32_t skc = skb[cur], svc = svb[cur];
#pragma unroll
        for (int ks = 0; ks < 4; ks++) {
            uint32_t kb[8][2];
            int rl = lane & 7, sel = (lane >> 3) & 1;
#pragma unroll
            for (int n = 0; n < 8; n++) {
                int rr = n * 8 + rl;
                LDSM2(kb[n], skc + rr * 128 + (((2 * ks + sel) ^ (rr & 7)) << 4));
            }
#pragma unroll
            for (int n = 0; n < 8; n++) mma16816(sacc[n], qf[ks], kb[n]);
        }

        // scale + causal mask (diagonal tile only)
#pragma unroll
        for (int n = 0; n < 8; n++)
#pragma unroll
            for (int e = 0; e < 4; e++) sacc[n][e] *= ATT_SCALE;
        if (causal && kt == qt) {
            int row0 = w * 16 + g;
#pragma unroll
            for (int n = 0; n < 8; n++) {
                int c0 = n * 8 + tig * 2;
                if (c0     > row0)     sacc[n][0] = -1e30f;
                if (c0 + 1 > row0)     sacc[n][1] = -1e30f;
                if (c0     > row0 + 8) sacc[n][2] = -1e30f;
                if (c0 + 1 > row0 + 8) sacc[n][3] = -1e30f;
            }
        }

        // online softmax
        float mx0 = -1e30f, mx1 = -1e30f;
#pragma unroll
        for (int n = 0; n < 8; n++) {
            mx0 = fmaxf(mx0, fmaxf(sacc[n][0], sacc[n][1]));
            mx1 = fmaxf(mx1, fmaxf(sacc[n][2], sacc[n][3]));
        }
        mx0 = fmaxf(mx0, __shfl_xor_sync(0xffffffffu, mx0, 1));
        mx0 = fmaxf(mx0, __shfl_xor_sync(0xffffffffu, mx0, 2));
        mx1 = fmaxf(mx1, __shfl_xor_sync(0xffffffffu, mx1, 1));
        mx1 = fmaxf(mx1, __shfl_xor_sync(0xffffffffu, mx1, 2));
        float mn0 = fmaxf(m0, mx0), mn1 = fmaxf(m1, mx1);
        float a0 = __expf(m0 - mn0), a1 = __expf(m1 - mn1);
        m0 = mn0; m1 = mn1;

        float ps0 = 0.f, ps1 = 0.f;
        uint32_t pf[4][4];
#pragma unroll
        for (int n = 0; n < 8; n++) {
            float p0 = __expf(sacc[n][0] - mn0), p1 = __expf(sacc[n][1] - mn0);
            float p2 = __expf(sacc[n][2] - mn1), p3 = __expf(sacc[n][3] - mn1);
            ps0 += p0 + p1; ps1 += p2 + p3;
            __half2 h01 = __floats2half2_rn(p0, p1);
            __half2 h23 = __floats2half2_rn(p2, p3);
            int ks = n >> 1, hi = (n & 1) * 2;
            pf[ks][hi]     = *(uint32_t*)&h01;
            pf[ks][hi + 1] = *(uint32_t*)&h23;
        }
        l0 = l0 * a0 + ps0;
        l1 = l1 * a1 + ps1;
#pragma unroll
        for (int n = 0; n < 8; n++) {
            oacc[n][0] *= a0; oacc[n][1] *= a0;
            oacc[n][2] *= a1; oacc[n][3] *= a1;
        }

        // O += P @ V  (V via ldmatrix.trans)
        {
            int rl = lane & 15, cs = lane >> 4;
#pragma unroll
            for (int np = 0; np < 4; np++) {
#pragma unroll
                for (int ks = 0; ks < 4; ks++) {
                    uint32_t vb[4];
                    int rr = ks * 16 + rl;
                    int ch = np * 2 + cs;
                    LDSM4T(vb, svc + rr * 128 + ((ch ^ (rr & 7)) << 4));
                    mma16816(oacc[2 * np],     pf[ks], vb);
                    mma16816(oacc[2 * np + 1], pf[ks], vb + 2);
                }
            }
        }

        CP_WAIT0();
        __syncthreads();
    }

    // epilogue
    l0 += __shfl_xor_sync(0xffffffffu, l0, 1);
    l0 += __shfl_xor_sync(0xffffffffu, l0, 2);
    l1 += __shfl_xor_sync(0xffffffffu, l1, 1);
    l1 += __shfl_xor_sync(0xffffffffu, l1, 2);
    float i0 = 1.f / l0, i1 = 1.f / l1;

    size_t base0 = ((size_t)(b * T + qt * 64 + w * 16 + g)) * E + h * HS;
    size_t base1 = base0 + (size_t)8 * E;
#pragma unroll
    for (int n = 0; n < 8; n++) {
        int c = n * 8 + tig * 2;
        float v0 = oacc[n][0] * i0, v1 = oacc[n][1] * i0;
        float v2 = oacc[n][2] * i1, v3 = oacc[n][3] * i1;
        __half2 h01 = __floats2half2_rn(v0, v1);
        __half2 h23 = __floats2half2_rn(v2, v3);
        *(__half2*)(Oh + base0 + c) = h01;
        *(__half2*)(Oh + base1 + c) = h23;
        float2 f01 = __half22float2(h01);
        float2 f23 = __half22float2(h23);
        *(__half2*)(Ol + base0 + c) = __floats2half2_rn(v0 - f01.x, v1 - f01.y);
        *(__half2*)(Ol + base1 + c) = __floats2half2_rn(v2 - f23.x, v3 - f23.y);
    }
}

// ---------------------------------------------------------------------------
// Weight transpose to fp16: out[C][R] = fp16(in[R][C])
// ---------------------------------------------------------------------------
__global__ void __launch_bounds__(256)
transpose_h_kernel(const float* __restrict__ in, __half* __restrict__ out,
                   int R, int C)
{
    __shared__ float t[32][33];
    int bx = blockIdx.x * 32, by = blockIdx.y * 32;
    int x = threadIdx.x, y = threadIdx.y;
#pragma unroll
    for (int j = 0; j < 32; j += 8)
        t[y + j][x] = in[(size_t)(by + y + j) * C + bx + x];
    __syncthreads();
#pragma unroll
    for (int j = 0; j < 32; j += 8)
        out[(size_t)(bx + y + j) * R + by + x] = __float2half(t[x][y + j]);
}

// ---------------------------------------------------------------------------
// fp32 -> hi/lo fp16 planes
// ---------------------------------------------------------------------------
__global__ void __launch_bounds__(256)
split_h_kernel(const float* __restrict__ in, __half* __restrict__ hi,
               __half* __restrict__ lo, int n)
{
    int i = blockIdx.x * 256 + threadIdx.x;
    if (i < n) {
        float v = in[i];
        __half h = __float2half(v);
        hi[i] = h;
        lo[i] = __float2half(v - __half2float(h));
    }
}

// ---------------------------------------------------------------------------
// Fused residual + LayerNorm: out = LN(x + r) * g + b  (+ optional hi/lo planes)
// ---------------------------------------------------------------------------
__global__ void __launch_bounds__(256)
ln_residual_kernel(const float* __restrict__ X, const float* __restrict__ R,
                   const float* __restrict__ G, const float* __restrict__ Bt,
                   float* __restrict__ Out, __half* __restrict__ Oh,
                   __half* __restrict__ Ol)
{
    const int N = E;
    int row = blockIdx.x;
    int tid = threadIdx.x;
    int lane = tid & 31, wid = tid >> 5;
    __shared__ float sm[8];
    __shared__ float stats[2];

    float v[4];
    float s = 0.f;
#pragma unroll
    for (int i = 0; i < 4; i++) {
        int idx = tid + i * 256;
        v[i] = X[(size_t)row * N + idx] + R[(size_t)row * N + idx];
        s += v[i];
    }
#pragma unroll
    for (int off = 16; off > 0; off >>= 1) s += __shfl_down_sync(0xffffffffu, s, off);
    if (lane == 0) sm[wid] = s;
    __syncthreads();
    if (tid == 0) {
        float t = 0.f;
#pragma unroll
        for (int i = 0; i < 8; i++) t += sm[i];
        stats[0] = t * (1.f / N);
    }
    __syncthreads();
    float mu = stats[0];

    float vs = 0.f;
#pragma unroll
    for (int i = 0; i < 4; i++) {
        float d = v[i] - mu;
        vs += d * d;
    }
#pragma unroll
    for (int off = 16; off > 0; off >>= 1) vs += __shfl_down_sync(0xffffffffu, vs, off);
    __syncthreads();
    if (lane == 0) sm[wid] = vs;
    __syncthreads();
    if (tid == 0) {
        float t = 0.f;
#pragma unroll
        for (int i = 0; i < 8; i++) t += sm[i];
        stats[1] = rsqrtf(t * (1.f / N) + LN_EPS);
    }
    __syncthreads();
    float rstd = stats[1];

#pragma unroll
    for (int i = 0; i < 4; i++) {
        int idx = tid + i * 256;
        float y = (v[i] - mu) * rstd * G[idx] + Bt[idx];
        Out[(size_t)row * N + idx] = y;
        if (Oh) {
            __half hh = __float2half(y);
            Oh[(size_t)row * N + idx] = hh;
            Ol[(size_t)row * N + idx] = __float2half(y - __half2float(hh));
        }
    }
}

// ---------------------------------------------------------------------------
// Launch
// ---------------------------------------------------------------------------
extern "C" void kernel_launch(void* const* d_in, const int* in_sizes, int n_in,
                              void* d_out, int out_size)
{
    const float* x       = (const float*)d_in[0];
    const float* context = (const float*)d_in[1];
    const float* sa_wq = (const float*)d_in[2];
    const float* sa_wk = (const float*)d_in[3];
    const float* sa_wv = (const float*)d_in[4];
    const float* sa_wo = (const float*)d_in[5];
    const float* sa_bo = (const float*)d_in[6];
    const float* ca_wq = (const float*)d_in[7];
    const float* ca_wk = (const float*)d_in[8];
    const float* ca_wv = (const float*)d_in[9];
    const float* ca_wo = (const float*)d_in[10];
    const float* ca_bo = (const float*)d_in[11];
    const float* n1_g  = (const float*)d_in[12];
    const float* n1_b  = (const float*)d_in[13];
    const float* n2_g  = (const float*)d_in[14];
    const float* n2_b  = (const float*)d_in[15];
    const float* n3_g  = (const float*)d_in[16];
    const float* n3_b  = (const float*)d_in[17];
    const float* ff_w1 = (const float*)d_in[18];
    const float* ff_b1 = (const float*)d_in[19];
    const float* ff_w2 = (const float*)d_in[20];
    const float* ff_b2 = (const float*)d_in[21];
    float* out = (float*)d_out;

    float *tmp_, *x1f_, *x2f_;
    cudaGetSymbolAddress((void**)&tmp_, g_tmp);
    cudaGetSymbolAddress((void**)&x1f_, g_x1f);
    cudaGetSymbolAddress((void**)&x2f_, g_x2f);

    __half *qh, *kh, *vh;
    cudaGetSymbolAddress((void**)&qh, g_qh);
    cudaGetSymbolAddress((void**)&kh, g_kh);
    cudaGetSymbolAddress((void**)&vh, g_vh);

    __half *xh, *xl, *ctxh, *ctxl, *x1h, *x1l, *x2h, *x2l, *ath, *atl, *ffh, *ffl;
    cudaGetSymbolAddress((void**)&xh,   g_xh);   cudaGetSymbolAddress((void**)&xl,   g_xl);
    cudaGetSymbolAddress((void**)&ctxh, g_ctxh); cudaGetSymbolAddress((void**)&ctxl, g_ctxl);
    cudaGetSymbolAddress((void**)&x1h,  g_x1h);  cudaGetSymbolAddress((void**)&x1l,  g_x1l);
    cudaGetSymbolAddress((void**)&x2h,  g_x2h);  cudaGetSymbolAddress((void**)&x2l,  g_x2l);
    cudaGetSymbolAddress((void**)&ath,  g_ath);  cudaGetSymbolAddress((void**)&atl,  g_atl);
    cudaGetSymbolAddress((void**)&ffh,  g_ffh);  cudaGetSymbolAddress((void**)&ffl,  g_ffl);

    __half *wqt, *wkt, *wvt, *wot, *cwqt, *cwkt, *cwvt, *cwot, *w1t, *w2t;
    cudaGetSymbolAddress((void**)&wqt,  g_sa_wqt); cudaGetSymbolAddress((void**)&wkt,  g_sa_wkt);
    cudaGetSymbolAddress((void**)&wvt,  g_sa_wvt); cudaGetSymbolAddress((void**)&wot,  g_sa_wot);
    cudaGetSymbolAddress((void**)&cwqt, g_ca_wqt); cudaGetSymbolAddress((void**)&cwkt, g_ca_wkt);
    cudaGetSymbolAddress((void**)&cwvt, g_ca_wvt); cudaGetSymbolAddress((void**)&cwot, g_ca_wot);
    cudaGetSymbolAddress((void**)&w1t,  g_w1t);    cudaGetSymbolAddress((void**)&w2t,  g_w2t);

    cudaFuncSetAttribute(hgemm_kernel,
                         cudaFuncAttributeMaxDynamicSharedMemorySize, GSMEM_SZ);

    dim3 tB(32, 8);
    dim3 tGee(E / 32, E / 32);
    dim3 tG1(HID / 32, E / 32);
    dim3 tG2(E / 32, HID / 32);
    transpose_h_kernel<<<tGee, tB>>>(sa_wq, wqt, E, E);
    transpose_h_kernel<<<tGee, tB>>>(sa_wk, wkt, E, E);
    transpose_h_kernel<<<tGee, tB>>>(sa_wv, wvt, E, E);
    transpose_h_kernel<<<tGee, tB>>>(sa_wo, wot, E, E);
    transpose_h_kernel<<<tGee, tB>>>(ca_wq, cwqt, E, E);
    transpose_h_kernel<<<tGee, tB>>>(ca_wk, cwkt, E, E);
    transpose_h_kernel<<<tGee, tB>>>(ca_wv, cwvt, E, E);
    transpose_h_kernel<<<tGee, tB>>>(ca_wo, cwot, E, E);
    transpose_h_kernel<<<tG1, tB>>>(ff_w1, w1t, E, HID);
    transpose_h_kernel<<<tG2, tB>>>(ff_w2, w2t, HID, E);

    int nElem = M_ROWS * E;
    split_h_kernel<<<nElem / 256, 256>>>(x, xh, xl, nElem);
    split_h_kernel<<<nElem / 256, 256>>>(context, ctxh, ctxl, nElem);

    dim3 gE(E / 128, M_ROWS / 128);
    dim3 gH(HID / 128, M_ROWS / 128);
    dim3 gFA(BATCH * NH, T / 64);

    // ---- Self-attention ----
    hgemm_kernel<<<gE, 256, GSMEM_SZ>>>(xh, xl, wqt, nullptr, nullptr, qh, nullptr, M_ROWS, E, E, 0);
    hgemm_kernel<<<gE, 256, GSMEM_SZ>>>(xh, xl, wkt, nullptr, nullptr, kh, nullptr, M_ROWS, E, E, 0);
    hgemm_kernel<<<gE, 256, GSMEM_SZ>>>(xh, xl, wvt, nullptr, nullptr, vh, nullptr, M_ROWS, E, E, 0);
    fa_mma_kernel<<<gFA, 128>>>(qh, kh, vh, ath, atl, 1);
    hgemm_kernel<<<gE, 256, GSMEM_SZ>>>(ath, atl, wot, sa_bo, tmp_, nullptr, nullptr, M_ROWS, E, E, 0);
    ln_residual_kernel<<<M_ROWS, 256>>>(x, tmp_, n1_g, n1_b, x1f_, x1h, x1l);

    // ---- Cross-attention ----
    hgemm_kernel<<<gE, 256, GSMEM_SZ>>>(x1h, x1l, cwqt, nullptr, nullptr, qh, nullptr, M_ROWS, E, E, 0);
    hgemm_kernel<<<gE, 256, GSMEM_SZ>>>(ctxh, ctxl, cwkt, nullptr, nullptr, kh, nullptr, M_ROWS, E, E, 0);
    hgemm_kernel<<<gE, 256, GSMEM_SZ>>>(ctxh, ctxl, cwvt, nullptr, nullptr, vh, nullptr, M_ROWS, E, E, 0);
    fa_mma_kernel<<<gFA, 128>>>(qh, kh, vh, ath, atl, 0);
    hgemm_kernel<<<gE, 256, GSMEM_SZ>>>(ath, atl, cwot, ca_bo, tmp_, nullptr, nullptr, M_ROWS, E, E, 0);
    ln_residual_kernel<<<M_ROWS, 256>>>(x1f_, tmp_, n2_g, n2_b, x2f_, x2h, x2l);

    // ---- FFN ----
    hgemm_kernel<<<gH, 256, GSMEM_SZ>>>(x2h, x2l, w1t, ff_b1, nullptr, ffh, ffl, M_ROWS, HID, E, 1);
    hgemm_kernel<<<gE, 256, GSMEM_SZ>>>(ffh, ffl, w2t, ff_b2, tmp_, nullptr, nullptr, M_ROWS, E, HID, 0);
    ln_residual_kernel<<<M_ROWS, 256>>>(x2f_, tmp_, n3_g, n3_b, out, nullptr, nullptr);
}

// round 5
// speedup vs baseline: 6.9445x; 1.2256x over previous
#include <cuda_runtime.h>
#include <cuda_fp16.h>
#include <math.h>
#include <stdint.h>

// Problem constants
#define BATCH 4
#define T 1024
#define E 1024
#define NH 16
#define HS 64
#define HID 4096
#define M_ROWS (BATCH * T)   // 4096
#define LN_EPS 1e-5f
#define ATT_SCALE 0.03125f   // E^-0.25 on q and k each -> E^-0.5 on dot

// ---------------------------------------------------------------------------
// Scratch (__device__ globals; no allocation allowed)
// ---------------------------------------------------------------------------
__device__ float  g_tmp[M_ROWS * E];
__device__ float  g_x1f[M_ROWS * E];
__device__ float  g_x2f[M_ROWS * E];
// fp16 q/k/v + attention out
__device__ __half g_qh[M_ROWS * E], g_kh[M_ROWS * E], g_vh[M_ROWS * E];
__device__ __half g_ath[M_ROWS * E];
// activation planes
__device__ __half g_xh[M_ROWS * E];
__device__ __half g_ctxh[M_ROWS * E];
__device__ __half g_x1h[M_ROWS * E];
__device__ __half g_x2h[M_ROWS * E],  g_x2l[M_ROWS * E];
__device__ __half g_ffh[M_ROWS * HID], g_ffl[M_ROWS * HID];
// fp16 transposed weights [N,K] (QKV packed for fused projections)
__device__ __half g_wqkv_sa[3 * E * E];         // wq^T | wk^T | wv^T
__device__ __half g_wq_ca[E * E];
__device__ __half g_wkv_ca[2 * E * E];          // wk^T | wv^T
__device__ __half g_sa_wot[E * E], g_ca_wot[E * E];
__device__ __half g_w1t[HID * E], g_w2t[E * HID];

// ---------------------------------------------------------------------------
// PTX helpers (sm_80+-compatible: cp.async, ldmatrix, mma.sync)
// ---------------------------------------------------------------------------
__device__ __forceinline__ uint32_t smem_u32(const void* p) {
    uint32_t a;
    asm("{ .reg .u64 t; cvta.to.shared.u64 t, %1; cvt.u32.u64 %0, t; }"
        : "=r"(a) : "l"(p));
    return a;
}

#define CP_ASYNC16(saddr, gptr) \
    asm volatile("cp.async.cg.shared.global [%0], [%1], 16;" \
        :: "r"(saddr), "l"(gptr) : "memory")
#define CP_COMMIT()  asm volatile("cp.async.commit_group;" ::: "memory")
#define CP_WAIT0()   asm volatile("cp.async.wait_group 0;" ::: "memory")

#define LDSM4(r, addr) \
    asm volatile("ldmatrix.sync.aligned.m8n8.x4.shared.b16 {%0,%1,%2,%3}, [%4];" \
        : "=r"((r)[0]), "=r"((r)[1]), "=r"((r)[2]), "=r"((r)[3]) : "r"(addr))
#define LDSM2(r, addr) \
    asm volatile("ldmatrix.sync.aligned.m8n8.x2.shared.b16 {%0,%1}, [%2];" \
        : "=r"((r)[0]), "=r"((r)[1]) : "r"(addr))
#define LDSM4T(r, addr) \
    asm volatile("ldmatrix.sync.aligned.m8n8.x4.trans.shared.b16 {%0,%1,%2,%3}, [%4];" \
        : "=r"((r)[0]), "=r"((r)[1]), "=r"((r)[2]), "=r"((r)[3]) : "r"(addr))

__device__ __forceinline__ void mma16816(float* c, const uint32_t* a, const uint32_t* b) {
    asm volatile(
        "mma.sync.aligned.m16n8k16.row.col.f32.f16.f16.f32 "
        "{%0,%1,%2,%3}, {%4,%5,%6,%7}, {%8,%9}, {%0,%1,%2,%3};"
        : "+f"(c[0]), "+f"(c[1]), "+f"(c[2]), "+f"(c[3])
        : "r"(a[0]), "r"(a[1]), "r"(a[2]), "r"(a[3]), "r"(b[0]), "r"(b[1]));
}

// ===========================================================================
// Single-plane HGEMM: C = Ah[M,K] @ Bt[N,K]^T (+bias)(+relu)
// Output: fp32 C32 (single dest) OR fp16 into up to 3 dest buffers selected
// by the N-tile index (bx / dstTiles), each with leading dim outLd.
// Tile 128x128x64, 256 threads, 2-stage cp.async, 64KB smem, 2 CTA/SM.
// ===========================================================================
#define HG1_STAGE 32768
#define HG1_SMEM  (2 * HG1_STAGE)

__global__ void __launch_bounds__(256, 2)
hgemm1_kernel(const __half* __restrict__ Ah, const __half* __restrict__ Bt,
              const float* __restrict__ bias, float* __restrict__ C32,
              __half* __restrict__ D0, __half* __restrict__ D1, __half* __restrict__ D2,
              int dstTiles, int outLd, int M, int N, int K, int relu)
{
    extern __shared__ char smem[];
    uint32_t sb = smem_u32(smem);
    int tid = threadIdx.x;
    int lane = tid & 31;
    int wid = tid >> 5;
    int wm = wid & 1, wn = wid >> 1;
    int bx = blockIdx.x, by = blockIdx.y;

    const __half* gA = Ah + (size_t)by * 128 * K;
    const __half* gB = Bt + (size_t)bx * 128 * K;

    int lrow = tid >> 3;
    int lch = tid & 7;
    uint32_t soff[4];
#pragma unroll
    for (int i = 0; i < 4; i++) {
        int r = lrow + 32 * i;
        soff[i] = (uint32_t)(r * 128 + ((lch ^ (r & 7)) * 16));
    }

    uint32_t aOff[4], aX[4], bOff[4], bX[4];
#pragma unroll
    for (int mf = 0; mf < 4; mf++) {
        int r = wm * 64 + mf * 16 + (lane & 15);
        aOff[mf] = r * 128; aX[mf] = r & 7;
    }
#pragma unroll
    for (int nf = 0; nf < 4; nf++) {
        int r = wn * 32 + nf * 8 + (lane & 7);
        bOff[nf] = r * 128; bX[nf] = r & 7;
    }
    int aSel = lane >> 4;
    int bSel = (lane >> 3) & 1;

    float acc[4][4][4];
#pragma unroll
    for (int mf = 0; mf < 4; mf++)
#pragma unroll
        for (int nf = 0; nf < 4; nf++)
#pragma unroll
            for (int r = 0; r < 4; r++) acc[mf][nf][r] = 0.f;

    const int KT = K >> 6;

    {
        uint32_t st = sb;
#pragma unroll
        for (int i = 0; i < 4; i++) {
            int r = lrow + 32 * i;
            CP_ASYNC16(st + soff[i],         gA + (size_t)r * K + lch * 8);
            CP_ASYNC16(st + 16384 + soff[i], gB + (size_t)r * K + lch * 8);
        }
        CP_COMMIT();
    }

    for (int kt = 0; kt < KT; kt++) {
        CP_WAIT0();
        __syncthreads();

        if (kt + 1 < KT) {
            uint32_t st = sb + ((kt + 1) & 1) * HG1_STAGE;
            int k0 = (kt + 1) << 6;
#pragma unroll
            for (int i = 0; i < 4; i++) {
                int r = lrow + 32 * i;
                CP_ASYNC16(st + soff[i],         gA + (size_t)r * K + k0 + lch * 8);
                CP_ASYNC16(st + 16384 + soff[i], gB + (size_t)r * K + k0 + lch * 8);
            }
            CP_COMMIT();
        }

        uint32_t aBase = sb + (kt & 1) * HG1_STAGE;
        uint32_t bBase = aBase + 16384;

#pragma unroll
        for (int ks = 0; ks < 4; ks++) {
            int cA = ks * 2 + aSel;
            int cB = ks * 2 + bSel;
            uint32_t a[4][4], b[4][2];
#pragma unroll
            for (int mf = 0; mf < 4; mf++)
                LDSM4(a[mf], aBase + aOff[mf] + ((cA ^ aX[mf]) << 4));
#pragma unroll
            for (int nf = 0; nf < 4; nf++)
                LDSM2(b[nf], bBase + bOff[nf] + ((cB ^ bX[nf]) << 4));
#pragma unroll
            for (int mf = 0; mf < 4; mf++)
#pragma unroll
                for (int nf = 0; nf < 4; nf++)
                    mma16816(acc[mf][nf], a[mf], b[nf]);
        }
        __syncthreads();
    }

    int g = lane >> 2, tig = lane & 3;
    int which = bx / dstTiles;
    int lbx = bx - which * dstTiles;
    __half* D = (which == 0) ? D0 : ((which == 1) ? D1 : D2);
#pragma unroll
    for (int mf = 0; mf < 4; mf++) {
#pragma unroll
        for (int nf = 0; nf < 4; nf++) {
            int r0 = by * 128 + wm * 64 + mf * 16 + g;
            int cl = wn * 32 + nf * 8 + tig * 2;
            int cglob = bx * 128 + cl;
            float b0 = 0.f, b1 = 0.f;
            if (bias) { b0 = bias[cglob]; b1 = bias[cglob + 1]; }
            float v0 = acc[mf][nf][0] + b0, v1 = acc[mf][nf][1] + b1;
            float v2 = acc[mf][nf][2] + b0, v3 = acc[mf][nf][3] + b1;
            if (relu) {
                v0 = fmaxf(v0, 0.f); v1 = fmaxf(v1, 0.f);
                v2 = fmaxf(v2, 0.f); v3 = fmaxf(v3, 0.f);
            }
            if (C32) {
                *(float2*)(C32 + (size_t)r0 * N + cglob) = make_float2(v0, v1);
                *(float2*)(C32 + (size_t)(r0 + 8) * N + cglob) = make_float2(v2, v3);
            } else {
                int c = lbx * 128 + cl;
                *(__half2*)(D + (size_t)r0 * outLd + c) = __floats2half2_rn(v0, v1);
                *(__half2*)(D + (size_t)(r0 + 8) * outLd + c) = __floats2half2_rn(v2, v3);
            }
        }
    }
}

// ===========================================================================
// Split-A HGEMM: C = (Ah+Al)[M,K] @ Bt[N,K]^T (+bias)(+relu)
// Output: fp32 C32 | hi/lo fp16 (Ch, Cl). 96KB smem, 1 CTA/SM.
// ===========================================================================
#define STAGE_BYTES 49152        // Ah 16K | Al 16K | B 16K
#define GSMEM_SZ    (2 * STAGE_BYTES)

__global__ void __launch_bounds__(256)
hgemm_kernel(const __half* __restrict__ Ah, const __half* __restrict__ Al,
             const __half* __restrict__ Bt, const float* __restrict__ bias,
             float* __restrict__ C32, __half* __restrict__ Ch, __half* __restrict__ Cl,
             int M, int N, int K, int relu)
{
    extern __shared__ char smem[];
    uint32_t sb = smem_u32(smem);
    int tid = threadIdx.x;
    int lane = tid & 31;
    int wid = tid >> 5;
    int wm = wid & 1, wn = wid >> 1;
    int bx = blockIdx.x, by = blockIdx.y;

    const __half* gA = Ah + (size_t)by * 128 * K;
    const __half* gAl = Al + (size_t)by * 128 * K;
    const __half* gB = Bt + (size_t)bx * 128 * K;

    int lrow = tid >> 3;
    int lch = tid & 7;
    uint32_t soff[4];
#pragma unroll
    for (int i = 0; i < 4; i++) {
        int r = lrow + 32 * i;
        soff[i] = (uint32_t)(r * 128 + ((lch ^ (r & 7)) * 16));
    }

    uint32_t aOff[4], aX[4], bOff[4], bX[4];
#pragma unroll
    for (int mf = 0; mf < 4; mf++) {
        int r = wm * 64 + mf * 16 + (lane & 15);
        aOff[mf] = r * 128; aX[mf] = r & 7;
    }
#pragma unroll
    for (int nf = 0; nf < 4; nf++) {
        int r = wn * 32 + nf * 8 + (lane & 7);
        bOff[nf] = r * 128; bX[nf] = r & 7;
    }
    int aSel = lane >> 4;
    int bSel = (lane >> 3) & 1;

    float acc[4][4][4];
#pragma unroll
    for (int mf = 0; mf < 4; mf++)
#pragma unroll
        for (int nf = 0; nf < 4; nf++)
#pragma unroll
            for (int r = 0; r < 4; r++) acc[mf][nf][r] = 0.f;

    const int KT = K >> 6;

    {
        uint32_t st = sb;
#pragma unroll
        for (int i = 0; i < 4; i++) {
            int r = lrow + 32 * i;
            CP_ASYNC16(st + soff[i],         gA  + (size_t)r * K + lch * 8);
            CP_ASYNC16(st + 16384 + soff[i], gAl + (size_t)r * K + lch * 8);
            CP_ASYNC16(st + 32768 + soff[i], gB  + (size_t)r * K + lch * 8);
        }
        CP_COMMIT();
    }

    for (int kt = 0; kt < KT; kt++) {
        CP_WAIT0();
        __syncthreads();

        if (kt + 1 < KT) {
            uint32_t st = sb + ((kt + 1) & 1) * STAGE_BYTES;
            int k0 = (kt + 1) << 6;
#pragma unroll
            for (int i = 0; i < 4; i++) {
                int r = lrow + 32 * i;
                CP_ASYNC16(st + soff[i],         gA  + (size_t)r * K + k0 + lch * 8);
                CP_ASYNC16(st + 16384 + soff[i], gAl + (size_t)r * K + k0 + lch * 8);
                CP_ASYNC16(st + 32768 + soff[i], gB  + (size_t)r * K + k0 + lch * 8);
            }
            CP_COMMIT();
        }

        uint32_t aBase = sb + (kt & 1) * STAGE_BYTES;
        uint32_t lBase = aBase + 16384;
        uint32_t bBase = aBase + 32768;

#pragma unroll
        for (int ks = 0; ks < 4; ks++) {
            int cA = ks * 2 + aSel;
            int cB = ks * 2 + bSel;
            uint32_t a[4][4], b[4][2];
#pragma unroll
            for (int mf = 0; mf < 4; mf++)
                LDSM4(a[mf], aBase + aOff[mf] + ((cA ^ aX[mf]) << 4));
#pragma unroll
            for (int nf = 0; nf < 4; nf++)
                LDSM2(b[nf], bBase + bOff[nf] + ((cB ^ bX[nf]) << 4));
#pragma unroll
            for (int mf = 0; mf < 4; mf++)
#pragma unroll
                for (int nf = 0; nf < 4; nf++)
                    mma16816(acc[mf][nf], a[mf], b[nf]);
            uint32_t al[4][4];
#pragma unroll
            for (int mf = 0; mf < 4; mf++)
                LDSM4(al[mf], lBase + aOff[mf] + ((cA ^ aX[mf]) << 4));
#pragma unroll
            for (int mf = 0; mf < 4; mf++)
#pragma unroll
                for (int nf = 0; nf < 4; nf++)
                    mma16816(acc[mf][nf], al[mf], b[nf]);
        }
        __syncthreads();
    }

    int g = lane >> 2, tig = lane & 3;
#pragma unroll
    for (int mf = 0; mf < 4; mf++) {
#pragma unroll
        for (int nf = 0; nf < 4; nf++) {
            int r0 = by * 128 + wm * 64 + mf * 16 + g;
            int c0 = bx * 128 + wn * 32 + nf * 8 + tig * 2;
            float b0 = 0.f, b1 = 0.f;
            if (bias) { b0 = bias[c0]; b1 = bias[c0 + 1]; }
            float v0 = acc[mf][nf][0] + b0, v1 = acc[mf][nf][1] + b1;
            float v2 = acc[mf][nf][2] + b0, v3 = acc[mf][nf][3] + b1;
            if (relu) {
                v0 = fmaxf(v0, 0.f); v1 = fmaxf(v1, 0.f);
                v2 = fmaxf(v2, 0.f); v3 = fmaxf(v3, 0.f);
            }
            if (C32) {
                *(float2*)(C32 + (size_t)r0 * N + c0) = make_float2(v0, v1);
                *(float2*)(C32 + (size_t)(r0 + 8) * N + c0) = make_float2(v2, v3);
            } else {
                __half h0 = __float2half(v0), h1 = __float2half(v1);
                __half h2 = __float2half(v2), h3 = __float2half(v3);
                *(__half2*)(Ch + (size_t)r0 * N + c0) = __halves2half2(h0, h1);
                *(__half2*)(Ch + (size_t)(r0 + 8) * N + c0) = __halves2half2(h2, h3);
                __half l0 = __float2half(v0 - __half2float(h0));
                __half l1 = __float2half(v1 - __half2float(h1));
                __half l2 = __float2half(v2 - __half2float(h2));
                __half l3 = __float2half(v3 - __half2float(h3));
                *(__half2*)(Cl + (size_t)r0 * N + c0) = __halves2half2(l0, l1);
                *(__half2*)(Cl + (size_t)(r0 + 8) * N + c0) = __halves2half2(l2, l3);
            }
        }
    }
}

// ---------------------------------------------------------------------------
// Tensor-core flash attention. grid (BATCH*NH, T/64), 128 threads.
// fp16 Q/K/V in, online softmax fp32, fp16 output (optional lo plane).
// ---------------------------------------------------------------------------
__global__ void __launch_bounds__(128)
fa_mma_kernel(const __half* __restrict__ Qm, const __half* __restrict__ Km,
              const __half* __restrict__ Vm, __half* __restrict__ Oh,
              __half* __restrict__ Ol, int causal)
{
    __shared__ __half sQ[64 * 64];
    __shared__ __half sK[2][64 * 64];
    __shared__ __half sV[2][64 * 64];

    int tid = threadIdx.x, lane = tid & 31, w = tid >> 5;
    int g = lane >> 2, tig = lane & 3;
    int bh = blockIdx.x, b = bh >> 4, h = bh & 15;
    int qt = blockIdx.y;

    uint32_t sq = smem_u32(sQ);
    uint32_t skb[2] = { smem_u32(sK[0]), smem_u32(sK[1]) };
    uint32_t svb[2] = { smem_u32(sV[0]), smem_u32(sV[1]) };

    const __half* Qg = Qm + ((size_t)(b * T + qt * 64)) * E + h * HS;
    const __half* K0 = Km + ((size_t)(b * T)) * E + h * HS;
    const __half* V0 = Vm + ((size_t)(b * T)) * E + h * HS;

#pragma unroll
    for (int i = 0; i < 4; i++) {
        int c = tid + i * 128; int r = c >> 3; int ch = c & 7;
        uint32_t off = r * 128 + ((ch ^ (r & 7)) << 4);
        CP_ASYNC16(sq + off, Qg + (size_t)r * E + ch * 8);
        CP_ASYNC16(skb[0] + off, K0 + (size_t)r * E + ch * 8);
        CP_ASYNC16(svb[0] + off, V0 + (size_t)r * E + ch * 8);
    }
    CP_COMMIT();
    CP_WAIT0();
    __syncthreads();

    uint32_t qf[4][4];
    {
        int r = w * 16 + (lane & 15); int sel = lane >> 4; int rx = r & 7;
        uint32_t ro = sq + r * 128;
#pragma unroll
        for (int ks = 0; ks < 4; ks++)
            LDSM4(qf[ks], ro + (((2 * ks + sel) ^ rx) << 4));
    }

    float oacc[8][4];
#pragma unroll
    for (int n = 0; n < 8; n++)
#pragma unroll
        for (int e = 0; e < 4; e++) oacc[n][e] = 0.f;
    float m0 = -1e30f, m1 = -1e30f, l0 = 0.f, l1 = 0.f;

    int nk = causal ? (qt + 1) : (T / 64);

    for (int kt = 0; kt < nk; kt++) {
        int cur = kt & 1;
        if (kt + 1 < nk) {
            int nst = cur ^ 1;
            const __half* Kg = Km + ((size_t)(b * T + (kt + 1) * 64)) * E + h * HS;
            const __half* Vg = Vm + ((size_t)(b * T + (kt + 1) * 64)) * E + h * HS;
#pragma unroll
            for (int i = 0; i < 4; i++) {
                int c = tid + i * 128; int r = c >> 3; int ch = c & 7;
                uint32_t off = r * 128 + ((ch ^ (r & 7)) << 4);
                CP_ASYNC16(skb[nst] + off, Kg + (size_t)r * E + ch * 8);
                CP_ASYNC16(svb[nst] + off, Vg + (size_t)r * E + ch * 8);
            }
            CP_COMMIT();
        }

        float sacc[8][4];
#pragma unroll
        for (int n = 0; n < 8; n++)
#pragma unroll
            for (int e = 0; e < 4; e++) sacc[n][e] = 0.f;

        uint32_t skc = skb[cur], svc = svb[cur];
#pragma unroll
        for (int ks = 0; ks < 4; ks++) {
            uint32_t kb[8][2];
            int rl = lane & 7, sel = (lane >> 3) & 1;
#pragma unroll
            for (int n = 0; n < 8; n++) {
                int rr = n * 8 + rl;
                LDSM2(kb[n], skc + rr * 128 + (((2 * ks + sel) ^ (rr & 7)) << 4));
            }
#pragma unroll
            for (int n = 0; n < 8; n++) mma16816(sacc[n], qf[ks], kb[n]);
        }

#pragma unroll
        for (int n = 0; n < 8; n++)
#pragma unroll
            for (int e = 0; e < 4; e++) sacc[n][e] *= ATT_SCALE;
        if (causal && kt == qt) {
            int row0 = w * 16 + g;
#pragma unroll
            for (int n = 0; n < 8; n++) {
                int c0 = n * 8 + tig * 2;
                if (c0     > row0)     sacc[n][0] = -1e30f;
                if (c0 + 1 > row0)     sacc[n][1] = -1e30f;
                if (c0     > row0 + 8) sacc[n][2] = -1e30f;
                if (c0 + 1 > row0 + 8) sacc[n][3] = -1e30f;
            }
        }

        float mx0 = -1e30f, mx1 = -1e30f;
#pragma unroll
        for (int n = 0; n < 8; n++) {
            mx0 = fmaxf(mx0, fmaxf(sacc[n][0], sacc[n][1]));
            mx1 = fmaxf(mx1, fmaxf(sacc[n][2], sacc[n][3]));
        }
        mx0 = fmaxf(mx0, __shfl_xor_sync(0xffffffffu, mx0, 1));
        mx0 = fmaxf(mx0, __shfl_xor_sync(0xffffffffu, mx0, 2));
        mx1 = fmaxf(mx1, __shfl_xor_sync(0xffffffffu, mx1, 1));
        mx1 = fmaxf(mx1, __shfl_xor_sync(0xffffffffu, mx1, 2));
        float mn0 = fmaxf(m0, mx0), mn1 = fmaxf(m1, mx1);
        float a0 = __expf(m0 - mn0), a1 = __expf(m1 - mn1);
        m0 = mn0; m1 = mn1;

        float ps0 = 0.f, ps1 = 0.f;
        uint32_t pf[4][4];
#pragma unroll
        for (int n = 0; n < 8; n++) {
            float p0 = __expf(sacc[n][0] - mn0), p1 = __expf(sacc[n][1] - mn0);
            float p2 = __expf(sacc[n][2] - mn1), p3 = __expf(sacc[n][3] - mn1);
            ps0 += p0 + p1; ps1 += p2 + p3;
            __half2 h01 = __floats2half2_rn(p0, p1);
            __half2 h23 = __floats2half2_rn(p2, p3);
            int ks = n >> 1, hi = (n & 1) * 2;
            pf[ks][hi]     = *(uint32_t*)&h01;
            pf[ks][hi + 1] = *(uint32_t*)&h23;
        }
        l0 = l0 * a0 + ps0;
        l1 = l1 * a1 + ps1;
#pragma unroll
        for (int n = 0; n < 8; n++) {
            oacc[n][0] *= a0; oacc[n][1] *= a0;
            oacc[n][2] *= a1; oacc[n][3] *= a1;
        }

        {
            int rl = lane & 15, cs = lane >> 4;
#pragma unroll
            for (int np = 0; np < 4; np++) {
#pragma unroll
                for (int ks = 0; ks < 4; ks++) {
                    uint32_t vb[4];
                    int rr = ks * 16 + rl;
                    int ch = np * 2 + cs;
                    LDSM4T(vb, svc + rr * 128 + ((ch ^ (rr & 7)) << 4));
                    mma16816(oacc[2 * np],     pf[ks], vb);
                    mma16816(oacc[2 * np + 1], pf[ks], vb + 2);
                }
            }
        }

        CP_WAIT0();
        __syncthreads();
    }

    l0 += __shfl_xor_sync(0xffffffffu, l0, 1);
    l0 += __shfl_xor_sync(0xffffffffu, l0, 2);
    l1 += __shfl_xor_sync(0xffffffffu, l1, 1);
    l1 += __shfl_xor_sync(0xffffffffu, l1, 2);
    float i0 = 1.f / l0, i1 = 1.f / l1;

    size_t base0 = ((size_t)(b * T + qt * 64 + w * 16 + g)) * E + h * HS;
    size_t base1 = base0 + (size_t)8 * E;
#pragma unroll
    for (int n = 0; n < 8; n++) {
        int c = n * 8 + tig * 2;
        float v0 = oacc[n][0] * i0, v1 = oacc[n][1] * i0;
        float v2 = oacc[n][2] * i1, v3 = oacc[n][3] * i1;
        __half2 h01 = __floats2half2_rn(v0, v1);
        __half2 h23 = __floats2half2_rn(v2, v3);
        *(__half2*)(Oh + base0 + c) = h01;
        *(__half2*)(Oh + base1 + c) = h23;
        if (Ol) {
            float2 f01 = __half22float2(h01);
            float2 f23 = __half22float2(h23);
            *(__half2*)(Ol + base0 + c) = __floats2half2_rn(v0 - f01.x, v1 - f01.y);
            *(__half2*)(Ol + base1 + c) = __floats2half2_rn(v2 - f23.x, v3 - f23.y);
        }
    }
}

// ---------------------------------------------------------------------------
// Weight transpose to fp16: out[C][R] = fp16(in[R][C])
// ---------------------------------------------------------------------------
__global__ void __launch_bounds__(256)
transpose_h_kernel(const float* __restrict__ in, __half* __restrict__ out,
                   int R, int C)
{
    __shared__ float t[32][33];
    int bx = blockIdx.x * 32, by = blockIdx.y * 32;
    int x = threadIdx.x, y = threadIdx.y;
#pragma unroll
    for (int j = 0; j < 32; j += 8)
        t[y + j][x] = in[(size_t)(by + y + j) * C + bx + x];
    __syncthreads();
#pragma unroll
    for (int j = 0; j < 32; j += 8)
        out[(size_t)(bx + y + j) * R + by + x] = __float2half(t[x][y + j]);
}

// ---------------------------------------------------------------------------
// fp32 -> fp16 (hi, optional lo)
// ---------------------------------------------------------------------------
__global__ void __launch_bounds__(256)
split_h_kernel(const float* __restrict__ in, __half* __restrict__ hi,
               __half* __restrict__ lo, int n)
{
    int i = blockIdx.x * 256 + threadIdx.x;
    if (i < n) {
        float v = in[i];
        __half h = __float2half(v);
        hi[i] = h;
        if (lo) lo[i] = __float2half(v - __half2float(h));
    }
}

// ---------------------------------------------------------------------------
// Fused residual + LayerNorm (+ optional fp16 hi / lo planes)
// ---------------------------------------------------------------------------
__global__ void __launch_bounds__(256)
ln_residual_kernel(const float* __restrict__ X, const float* __restrict__ R,
                   const float* __restrict__ G, const float* __restrict__ Bt,
                   float* __restrict__ Out, __half* __restrict__ Oh,
                   __half* __restrict__ Ol)
{
    const int N = E;
    int row = blockIdx.x;
    int tid = threadIdx.x;
    int lane = tid & 31, wid = tid >> 5;
    __shared__ float sm[8];
    __shared__ float stats[2];

    float v[4];
    float s = 0.f;
#pragma unroll
    for (int i = 0; i < 4; i++) {
        int idx = tid + i * 256;
        v[i] = X[(size_t)row * N + idx] + R[(size_t)row * N + idx];
        s += v[i];
    }
#pragma unroll
    for (int off = 16; off > 0; off >>= 1) s += __shfl_down_sync(0xffffffffu, s, off);
    if (lane == 0) sm[wid] = s;
    __syncthreads();
    if (tid == 0) {
        float t = 0.f;
#pragma unroll
        for (int i = 0; i < 8; i++) t += sm[i];
        stats[0] = t * (1.f / N);
    }
    __syncthreads();
    float mu = stats[0];

    float vs = 0.f;
#pragma unroll
    for (int i = 0; i < 4; i++) {
        float d = v[i] - mu;
        vs += d * d;
    }
#pragma unroll
    for (int off = 16; off > 0; off >>= 1) vs += __shfl_down_sync(0xffffffffu, vs, off);
    __syncthreads();
    if (lane == 0) sm[wid] = vs;
    __syncthreads();
    if (tid == 0) {
        float t = 0.f;
#pragma unroll
        for (int i = 0; i < 8; i++) t += sm[i];
        stats[1] = rsqrtf(t * (1.f / N) + LN_EPS);
    }
    __syncthreads();
    float rstd = stats[1];

#pragma unroll
    for (int i = 0; i < 4; i++) {
        int idx = tid + i * 256;
        float y = (v[i] - mu) * rstd * G[idx] + Bt[idx];
        Out[(size_t)row * N + idx] = y;
        if (Oh) {
            __half hh = __float2half(y);
            Oh[(size_t)row * N + idx] = hh;
            if (Ol) Ol[(size_t)row * N + idx] = __float2half(y - __half2float(hh));
        }
    }
}

// ---------------------------------------------------------------------------
// Launch
// ---------------------------------------------------------------------------
extern "C" void kernel_launch(void* const* d_in, const int* in_sizes, int n_in,
                              void* d_out, int out_size)
{
    const float* x       = (const float*)d_in[0];
    const float* context = (const float*)d_in[1];
    const float* sa_wq = (const float*)d_in[2];
    const float* sa_wk = (const float*)d_in[3];
    const float* sa_wv = (const float*)d_in[4];
    const float* sa_wo = (const float*)d_in[5];
    const float* sa_bo = (const float*)d_in[6];
    const float* ca_wq = (const float*)d_in[7];
    const float* ca_wk = (const float*)d_in[8];
    const float* ca_wv = (const float*)d_in[9];
    const float* ca_wo = (const float*)d_in[10];
    const float* ca_bo = (const float*)d_in[11];
    const float* n1_g  = (const float*)d_in[12];
    const float* n1_b  = (const float*)d_in[13];
    const float* n2_g  = (const float*)d_in[14];
    const float* n2_b  = (const float*)d_in[15];
    const float* n3_g  = (const float*)d_in[16];
    const float* n3_b  = (const float*)d_in[17];
    const float* ff_w1 = (const float*)d_in[18];
    const float* ff_b1 = (const float*)d_in[19];
    const float* ff_w2 = (const float*)d_in[20];
    const float* ff_b2 = (const float*)d_in[21];
    float* out = (float*)d_out;

    float *tmp_, *x1f_, *x2f_;
    cudaGetSymbolAddress((void**)&tmp_, g_tmp);
    cudaGetSymbolAddress((void**)&x1f_, g_x1f);
    cudaGetSymbolAddress((void**)&x2f_, g_x2f);

    __half *qh, *kh, *vh, *ath;
    cudaGetSymbolAddress((void**)&qh,  g_qh);
    cudaGetSymbolAddress((void**)&kh,  g_kh);
    cudaGetSymbolAddress((void**)&vh,  g_vh);
    cudaGetSymbolAddress((void**)&ath, g_ath);

    __half *xh, *ctxh, *x1h, *x2h, *x2l, *ffh, *ffl;
    cudaGetSymbolAddress((void**)&xh,   g_xh);
    cudaGetSymbolAddress((void**)&ctxh, g_ctxh);
    cudaGetSymbolAddress((void**)&x1h,  g_x1h);
    cudaGetSymbolAddress((void**)&x2h,  g_x2h);  cudaGetSymbolAddress((void**)&x2l,  g_x2l);
    cudaGetSymbolAddress((void**)&ffh,  g_ffh);  cudaGetSymbolAddress((void**)&ffl,  g_ffl);

    __half *wqkv, *wqca, *wkvca, *wot, *cwot, *w1t, *w2t;
    cudaGetSymbolAddress((void**)&wqkv,  g_wqkv_sa);
    cudaGetSymbolAddress((void**)&wqca,  g_wq_ca);
    cudaGetSymbolAddress((void**)&wkvca, g_wkv_ca);
    cudaGetSymbolAddress((void**)&wot,   g_sa_wot);
    cudaGetSymbolAddress((void**)&cwot,  g_ca_wot);
    cudaGetSymbolAddress((void**)&w1t,   g_w1t);
    cudaGetSymbolAddress((void**)&w2t,   g_w2t);

    cudaFuncSetAttribute(hgemm_kernel,
                         cudaFuncAttributeMaxDynamicSharedMemorySize, GSMEM_SZ);
    cudaFuncSetAttribute(hgemm1_kernel,
                         cudaFuncAttributeMaxDynamicSharedMemorySize, HG1_SMEM);

    dim3 tB(32, 8);
    dim3 tGee(E / 32, E / 32);
    dim3 tG1(HID / 32, E / 32);
    dim3 tG2(E / 32, HID / 32);
    // SA QKV packed [3E, E]
    transpose_h_kernel<<<tGee, tB>>>(sa_wq, wqkv,             E, E);
    transpose_h_kernel<<<tGee, tB>>>(sa_wk, wqkv + E * E,     E, E);
    transpose_h_kernel<<<tGee, tB>>>(sa_wv, wqkv + 2 * E * E, E, E);
    transpose_h_kernel<<<tGee, tB>>>(sa_wo, wot, E, E);
    // CA: Q alone, K|V packed [2E, E]
    transpose_h_kernel<<<tGee, tB>>>(ca_wq, wqca, E, E);
    transpose_h_kernel<<<tGee, tB>>>(ca_wk, wkvca,         E, E);
    transpose_h_kernel<<<tGee, tB>>>(ca_wv, wkvca + E * E, E, E);
    transpose_h_kernel<<<tGee, tB>>>(ca_wo, cwot, E, E);
    transpose_h_kernel<<<tG1, tB>>>(ff_w1, w1t, E, HID);
    transpose_h_kernel<<<tG2, tB>>>(ff_w2, w2t, HID, E);

    int nElem = M_ROWS * E;
    split_h_kernel<<<nElem / 256, 256>>>(x, xh, nullptr, nElem);
    split_h_kernel<<<nElem / 256, 256>>>(context, ctxh, nullptr, nElem);

    dim3 gQKV(3 * E / 128, M_ROWS / 128);   // 24 x 32
    dim3 gKV(2 * E / 128, M_ROWS / 128);    // 16 x 32
    dim3 gE(E / 128, M_ROWS / 128);         // 8 x 32
    dim3 gH(HID / 128, M_ROWS / 128);       // 32 x 32
    dim3 gFA(BATCH * NH, T / 64);

    // ---- Self-attention ----
    hgemm1_kernel<<<gQKV, 256, HG1_SMEM>>>(xh, wqkv, nullptr, nullptr,
                                           qh, kh, vh, 8, E, M_ROWS, 3 * E, E, 0);
    fa_mma_kernel<<<gFA, 128>>>(qh, kh, vh, ath, nullptr, 1);
    hgemm1_kernel<<<gE, 256, HG1_SMEM>>>(ath, wot, sa_bo, tmp_,
                                         nullptr, nullptr, nullptr, 8, E, M_ROWS, E, E, 0);
    ln_residual_kernel<<<M_ROWS, 256>>>(x, tmp_, n1_g, n1_b, x1f_, x1h, nullptr);

    // ---- Cross-attention ----
    hgemm1_kernel<<<gE, 256, HG1_SMEM>>>(x1h, wqca, nullptr, nullptr,
                                         qh, nullptr, nullptr, 8, E, M_ROWS, E, E, 0);
    hgemm1_kernel<<<gKV, 256, HG1_SMEM>>>(ctxh, wkvca, nullptr, nullptr,
                                          kh, vh, nullptr, 8, E, M_ROWS, 2 * E, E, 0);
    fa_mma_kernel<<<gFA, 128>>>(qh, kh, vh, ath, nullptr, 0);
    hgemm1_kernel<<<gE, 256, HG1_SMEM>>>(ath, cwot, ca_bo, tmp_,
                                         nullptr, nullptr, nullptr, 8, E, M_ROWS, E, E, 0);
    ln_residual_kernel<<<M_ROWS, 256>>>(x1f_, tmp_, n2_g, n2_b, x2f_, x2h, x2l);

    // ---- FFN (split path for accuracy) ----
    hgemm_kernel<<<gH, 256, GSMEM_SZ>>>(x2h, x2l, w1t, ff_b1, nullptr, ffh, ffl,
                                        M_ROWS, HID, E, 1);
    hgemm_kernel<<<gE, 256, GSMEM_SZ>>>(ffh, ffl, w2t, ff_b2, tmp_, nullptr, nullptr,
                                        M_ROWS, E, HID, 0);
    ln_residual_kernel<<<M_ROWS, 256>>>(x2f_, tmp_, n3_g, n3_b, out, nullptr, nullptr);
}

// round 6
// speedup vs baseline: 8.6219x; 1.2415x over previous
#include <cuda_runtime.h>
#include <cuda_fp16.h>
#include <math.h>
#include <stdint.h>

// Problem constants
#define BATCH 4
#define T 1024
#define E 1024
#define NH 16
#define HS 64
#define HID 4096
#define M_ROWS (BATCH * T)   // 4096
#define LN_EPS 1e-5f
#define ATT_SCALE 0.03125f   // E^-0.25 on q and k each -> E^-0.5 on dot

// ---------------------------------------------------------------------------
// Scratch (__device__ globals; no allocation allowed)
// ---------------------------------------------------------------------------
__device__ float  g_tmp[M_ROWS * E];
__device__ float  g_x1f[M_ROWS * E];
__device__ float  g_x2f[M_ROWS * E];
__device__ __half g_qh[M_ROWS * E], g_kh[M_ROWS * E], g_vh[M_ROWS * E];
__device__ __half g_ath[M_ROWS * E];
__device__ __half g_xh[M_ROWS * E];
__device__ __half g_ctxh[M_ROWS * E];
__device__ __half g_x1h[M_ROWS * E];
__device__ __half g_x2h[M_ROWS * E];
__device__ __half g_ffh[M_ROWS * HID];
// fp16 transposed weights [N,K] (QKV packed for fused projections)
__device__ __half g_wqkv_sa[3 * E * E];         // wq^T | wk^T | wv^T
__device__ __half g_wq_ca[E * E];
__device__ __half g_wkv_ca[2 * E * E];          // wk^T | wv^T
__device__ __half g_sa_wot[E * E], g_ca_wot[E * E];
__device__ __half g_w1t[HID * E], g_w2t[E * HID];

// ---------------------------------------------------------------------------
// PTX helpers (sm_80+-compatible: cp.async, ldmatrix, mma.sync)
// ---------------------------------------------------------------------------
__device__ __forceinline__ uint32_t smem_u32(const void* p) {
    uint32_t a;
    asm("{ .reg .u64 t; cvta.to.shared.u64 t, %1; cvt.u32.u64 %0, t; }"
        : "=r"(a) : "l"(p));
    return a;
}

#define CP_ASYNC16(saddr, gptr) \
    asm volatile("cp.async.cg.shared.global [%0], [%1], 16;" \
        :: "r"(saddr), "l"(gptr) : "memory")
#define CP_COMMIT()  asm volatile("cp.async.commit_group;" ::: "memory")
#define CP_WAIT0()   asm volatile("cp.async.wait_group 0;" ::: "memory")

#define LDSM4(r, addr) \
    asm volatile("ldmatrix.sync.aligned.m8n8.x4.shared.b16 {%0,%1,%2,%3}, [%4];" \
        : "=r"((r)[0]), "=r"((r)[1]), "=r"((r)[2]), "=r"((r)[3]) : "r"(addr))
#define LDSM2(r, addr) \
    asm volatile("ldmatrix.sync.aligned.m8n8.x2.shared.b16 {%0,%1}, [%2];" \
        : "=r"((r)[0]), "=r"((r)[1]) : "r"(addr))
#define LDSM4T(r, addr) \
    asm volatile("ldmatrix.sync.aligned.m8n8.x4.trans.shared.b16 {%0,%1,%2,%3}, [%4];" \
        : "=r"((r)[0]), "=r"((r)[1]), "=r"((r)[2]), "=r"((r)[3]) : "r"(addr))

__device__ __forceinline__ void mma16816(float* c, const uint32_t* a, const uint32_t* b) {
    asm volatile(
        "mma.sync.aligned.m16n8k16.row.col.f32.f16.f16.f32 "
        "{%0,%1,%2,%3}, {%4,%5,%6,%7}, {%8,%9}, {%0,%1,%2,%3};"
        : "+f"(c[0]), "+f"(c[1]), "+f"(c[2]), "+f"(c[3])
        : "r"(a[0]), "r"(a[1]), "r"(a[2]), "r"(a[3]), "r"(b[0]), "r"(b[1]));
}

// ===========================================================================
// Single-plane HGEMM: C = Ah[M,K] @ Bt[N,K]^T (+bias)(+relu)
// Output: fp32 C32 (single dest) OR fp16 into up to 3 dest buffers selected
// by the N-tile index (bx / dstTiles), each with leading dim outLd.
// Tile 128x128x64, 256 threads, 2-stage cp.async, 64KB smem, 2 CTA/SM.
// ===========================================================================
#define HG1_STAGE 32768
#define HG1_SMEM  (2 * HG1_STAGE)

__global__ void __launch_bounds__(256, 2)
hgemm1_kernel(const __half* __restrict__ Ah, const __half* __restrict__ Bt,
              const float* __restrict__ bias, float* __restrict__ C32,
              __half* __restrict__ D0, __half* __restrict__ D1, __half* __restrict__ D2,
              int dstTiles, int outLd, int M, int N, int K, int relu)
{
    extern __shared__ char smem[];
    uint32_t sb = smem_u32(smem);
    int tid = threadIdx.x;
    int lane = tid & 31;
    int wid = tid >> 5;
    int wm = wid & 1, wn = wid >> 1;
    int bx = blockIdx.x, by = blockIdx.y;

    const __half* gA = Ah + (size_t)by * 128 * K;
    const __half* gB = Bt + (size_t)bx * 128 * K;

    int lrow = tid >> 3;
    int lch = tid & 7;
    uint32_t soff[4];
#pragma unroll
    for (int i = 0; i < 4; i++) {
        int r = lrow + 32 * i;
        soff[i] = (uint32_t)(r * 128 + ((lch ^ (r & 7)) * 16));
    }

    uint32_t aOff[4], aX[4], bOff[4], bX[4];
#pragma unroll
    for (int mf = 0; mf < 4; mf++) {
        int r = wm * 64 + mf * 16 + (lane & 15);
        aOff[mf] = r * 128; aX[mf] = r & 7;
    }
#pragma unroll
    for (int nf = 0; nf < 4; nf++) {
        int r = wn * 32 + nf * 8 + (lane & 7);
        bOff[nf] = r * 128; bX[nf] = r & 7;
    }
    int aSel = lane >> 4;
    int bSel = (lane >> 3) & 1;

    float acc[4][4][4];
#pragma unroll
    for (int mf = 0; mf < 4; mf++)
#pragma unroll
        for (int nf = 0; nf < 4; nf++)
#pragma unroll
            for (int r = 0; r < 4; r++) acc[mf][nf][r] = 0.f;

    const int KT = K >> 6;

    {
        uint32_t st = sb;
#pragma unroll
        for (int i = 0; i < 4; i++) {
            int r = lrow + 32 * i;
            CP_ASYNC16(st + soff[i],         gA + (size_t)r * K + lch * 8);
            CP_ASYNC16(st + 16384 + soff[i], gB + (size_t)r * K + lch * 8);
        }
        CP_COMMIT();
    }

    for (int kt = 0; kt < KT; kt++) {
        CP_WAIT0();
        __syncthreads();

        if (kt + 1 < KT) {
            uint32_t st = sb + ((kt + 1) & 1) * HG1_STAGE;
            int k0 = (kt + 1) << 6;
#pragma unroll
            for (int i = 0; i < 4; i++) {
                int r = lrow + 32 * i;
                CP_ASYNC16(st + soff[i],         gA + (size_t)r * K + k0 + lch * 8);
                CP_ASYNC16(st + 16384 + soff[i], gB + (size_t)r * K + k0 + lch * 8);
            }
            CP_COMMIT();
        }

        uint32_t aBase = sb + (kt & 1) * HG1_STAGE;
        uint32_t bBase = aBase + 16384;

#pragma unroll
        for (int ks = 0; ks < 4; ks++) {
            int cA = ks * 2 + aSel;
            int cB = ks * 2 + bSel;
            uint32_t a[4][4], b[4][2];
#pragma unroll
            for (int mf = 0; mf < 4; mf++)
                LDSM4(a[mf], aBase + aOff[mf] + ((cA ^ aX[mf]) << 4));
#pragma unroll
            for (int nf = 0; nf < 4; nf++)
                LDSM2(b[nf], bBase + bOff[nf] + ((cB ^ bX[nf]) << 4));
#pragma unroll
            for (int mf = 0; mf < 4; mf++)
#pragma unroll
                for (int nf = 0; nf < 4; nf++)
                    mma16816(acc[mf][nf], a[mf], b[nf]);
        }
        __syncthreads();
    }

    int g = lane >> 2, tig = lane & 3;
    int which = bx / dstTiles;
    int lbx = bx - which * dstTiles;
    __half* D = (which == 0) ? D0 : ((which == 1) ? D1 : D2);
#pragma unroll
    for (int mf = 0; mf < 4; mf++) {
#pragma unroll
        for (int nf = 0; nf < 4; nf++) {
            int r0 = by * 128 + wm * 64 + mf * 16 + g;
            int cl = wn * 32 + nf * 8 + tig * 2;
            int cglob = bx * 128 + cl;
            float b0 = 0.f, b1 = 0.f;
            if (bias) { b0 = bias[cglob]; b1 = bias[cglob + 1]; }
            float v0 = acc[mf][nf][0] + b0, v1 = acc[mf][nf][1] + b1;
            float v2 = acc[mf][nf][2] + b0, v3 = acc[mf][nf][3] + b1;
            if (relu) {
                v0 = fmaxf(v0, 0.f); v1 = fmaxf(v1, 0.f);
                v2 = fmaxf(v2, 0.f); v3 = fmaxf(v3, 0.f);
            }
            if (C32) {
                *(float2*)(C32 + (size_t)r0 * N + cglob) = make_float2(v0, v1);
                *(float2*)(C32 + (size_t)(r0 + 8) * N + cglob) = make_float2(v2, v3);
            } else {
                int c = lbx * 128 + cl;
                *(__half2*)(D + (size_t)r0 * outLd + c) = __floats2half2_rn(v0, v1);
                *(__half2*)(D + (size_t)(r0 + 8) * outLd + c) = __floats2half2_rn(v2, v3);
            }
        }
    }
}

// ---------------------------------------------------------------------------
// Tensor-core flash attention. grid (BATCH*NH, T/64), 128 threads.
// ---------------------------------------------------------------------------
__global__ void __launch_bounds__(128)
fa_mma_kernel(const __half* __restrict__ Qm, const __half* __restrict__ Km,
              const __half* __restrict__ Vm, __half* __restrict__ Oh, int causal)
{
    __shared__ __half sQ[64 * 64];
    __shared__ __half sK[2][64 * 64];
    __shared__ __half sV[2][64 * 64];

    int tid = threadIdx.x, lane = tid & 31, w = tid >> 5;
    int g = lane >> 2, tig = lane & 3;
    int bh = blockIdx.x, b = bh >> 4, h = bh & 15;
    int qt = blockIdx.y;

    uint32_t sq = smem_u32(sQ);
    uint32_t skb[2] = { smem_u32(sK[0]), smem_u32(sK[1]) };
    uint32_t svb[2] = { smem_u32(sV[0]), smem_u32(sV[1]) };

    const __half* Qg = Qm + ((size_t)(b * T + qt * 64)) * E + h * HS;
    const __half* K0 = Km + ((size_t)(b * T)) * E + h * HS;
    const __half* V0 = Vm + ((size_t)(b * T)) * E + h * HS;

#pragma unroll
    for (int i = 0; i < 4; i++) {
        int c = tid + i * 128; int r = c >> 3; int ch = c & 7;
        uint32_t off = r * 128 + ((ch ^ (r & 7)) << 4);
        CP_ASYNC16(sq + off, Qg + (size_t)r * E + ch * 8);
        CP_ASYNC16(skb[0] + off, K0 + (size_t)r * E + ch * 8);
        CP_ASYNC16(svb[0] + off, V0 + (size_t)r * E + ch * 8);
    }
    CP_COMMIT();
    CP_WAIT0();
    __syncthreads();

    uint32_t qf[4][4];
    {
        int r = w * 16 + (lane & 15); int sel = lane >> 4; int rx = r & 7;
        uint32_t ro = sq + r * 128;
#pragma unroll
        for (int ks = 0; ks < 4; ks++)
            LDSM4(qf[ks], ro + (((2 * ks + sel) ^ rx) << 4));
    }

    float oacc[8][4];
#pragma unroll
    for (int n = 0; n < 8; n++)
#pragma unroll
        for (int e = 0; e < 4; e++) oacc[n][e] = 0.f;
    float m0 = -1e30f, m1 = -1e30f, l0 = 0.f, l1 = 0.f;

    int nk = causal ? (qt + 1) : (T / 64);

    for (int kt = 0; kt < nk; kt++) {
        int cur = kt & 1;
        if (kt + 1 < nk) {
            int nst = cur ^ 1;
            const __half* Kg = Km + ((size_t)(b * T + (kt + 1) * 64)) * E + h * HS;
            const __half* Vg = Vm + ((size_t)(b * T + (kt + 1) * 64)) * E + h * HS;
#pragma unroll
            for (int i = 0; i < 4; i++) {
                int c = tid + i * 128; int r = c >> 3; int ch = c & 7;
                uint32_t off = r * 128 + ((ch ^ (r & 7)) << 4);
                CP_ASYNC16(skb[nst] + off, Kg + (size_t)r * E + ch * 8);
                CP_ASYNC16(svb[nst] + off, Vg + (size_t)r * E + ch * 8);
            }
            CP_COMMIT();
        }

        float sacc[8][4];
#pragma unroll
        for (int n = 0; n < 8; n++)
#pragma unroll
            for (int e = 0; e < 4; e++) sacc[n][e] = 0.f;

        uint32_t skc = skb[cur], svc = svb[cur];
#pragma unroll
        for (int ks = 0; ks < 4; ks++) {
            uint32_t kb[8][2];
            int rl = lane & 7, sel = (lane >> 3) & 1;
#pragma unroll
            for (int n = 0; n < 8; n++) {
                int rr = n * 8 + rl;
                LDSM2(kb[n], skc + rr * 128 + (((2 * ks + sel) ^ (rr & 7)) << 4));
            }
#pragma unroll
            for (int n = 0; n < 8; n++) mma16816(sacc[n], qf[ks], kb[n]);
        }

#pragma unroll
        for (int n = 0; n < 8; n++)
#pragma unroll
            for (int e = 0; e < 4; e++) sacc[n][e] *= ATT_SCALE;
        if (causal && kt == qt) {
            int row0 = w * 16 + g;
#pragma unroll
            for (int n = 0; n < 8; n++) {
                int c0 = n * 8 + tig * 2;
                if (c0     > row0)     sacc[n][0] = -1e30f;
                if (c0 + 1 > row0)     sacc[n][1] = -1e30f;
                if (c0     > row0 + 8) sacc[n][2] = -1e30f;
                if (c0 + 1 > row0 + 8) sacc[n][3] = -1e30f;
            }
        }

        float mx0 = -1e30f, mx1 = -1e30f;
#pragma unroll
        for (int n = 0; n < 8; n++) {
            mx0 = fmaxf(mx0, fmaxf(sacc[n][0], sacc[n][1]));
            mx1 = fmaxf(mx1, fmaxf(sacc[n][2], sacc[n][3]));
        }
        mx0 = fmaxf(mx0, __shfl_xor_sync(0xffffffffu, mx0, 1));
        mx0 = fmaxf(mx0, __shfl_xor_sync(0xffffffffu, mx0, 2));
        mx1 = fmaxf(mx1, __shfl_xor_sync(0xffffffffu, mx1, 1));
        mx1 = fmaxf(mx1, __shfl_xor_sync(0xffffffffu, mx1, 2));
        float mn0 = fmaxf(m0, mx0), mn1 = fmaxf(m1, mx1);
        float a0 = __expf(m0 - mn0), a1 = __expf(m1 - mn1);
        m0 = mn0; m1 = mn1;

        float ps0 = 0.f, ps1 = 0.f;
        uint32_t pf[4][4];
#pragma unroll
        for (int n = 0; n < 8; n++) {
            float p0 = __expf(sacc[n][0] - mn0), p1 = __expf(sacc[n][1] - mn0);
            float p2 = __expf(sacc[n][2] - mn1), p3 = __expf(sacc[n][3] - mn1);
            ps0 += p0 + p1; ps1 += p2 + p3;
            __half2 h01 = __floats2half2_rn(p0, p1);
            __half2 h23 = __floats2half2_rn(p2, p3);
            int ks = n >> 1, hi = (n & 1) * 2;
            pf[ks][hi]     = *(uint32_t*)&h01;
            pf[ks][hi + 1] = *(uint32_t*)&h23;
        }
        l0 = l0 * a0 + ps0;
        l1 = l1 * a1 + ps1;
#pragma unroll
        for (int n = 0; n < 8; n++) {
            oacc[n][0] *= a0; oacc[n][1] *= a0;
            oacc[n][2] *= a1; oacc[n][3] *= a1;
        }

        {
            int rl = lane & 15, cs = lane >> 4;
#pragma unroll
            for (int np = 0; np < 4; np++) {
#pragma unroll
                for (int ks = 0; ks < 4; ks++) {
                    uint32_t vb[4];
                    int rr = ks * 16 + rl;
                    int ch = np * 2 + cs;
                    LDSM4T(vb, svc + rr * 128 + ((ch ^ (rr & 7)) << 4));
                    mma16816(oacc[2 * np],     pf[ks], vb);
                    mma16816(oacc[2 * np + 1], pf[ks], vb + 2);
                }
            }
        }

        CP_WAIT0();
        __syncthreads();
    }

    l0 += __shfl_xor_sync(0xffffffffu, l0, 1);
    l0 += __shfl_xor_sync(0xffffffffu, l0, 2);
    l1 += __shfl_xor_sync(0xffffffffu, l1, 1);
    l1 += __shfl_xor_sync(0xffffffffu, l1, 2);
    float i0 = 1.f / l0, i1 = 1.f / l1;

    size_t base0 = ((size_t)(b * T + qt * 64 + w * 16 + g)) * E + h * HS;
    size_t base1 = base0 + (size_t)8 * E;
#pragma unroll
    for (int n = 0; n < 8; n++) {
        int c = n * 8 + tig * 2;
        *(__half2*)(Oh + base0 + c) = __floats2half2_rn(oacc[n][0] * i0, oacc[n][1] * i0);
        *(__half2*)(Oh + base1 + c) = __floats2half2_rn(oacc[n][2] * i1, oacc[n][3] * i1);
    }
}

// ---------------------------------------------------------------------------
// Batched weight transpose to fp16 (8 equal E x E matrices, one launch)
// ---------------------------------------------------------------------------
struct TP8 { const float* s[8]; __half* d[8]; };

__global__ void __launch_bounds__(256)
transpose8_kernel(TP8 p)
{
    __shared__ float t[32][33];
    const float* in = p.s[blockIdx.z];
    __half* out = p.d[blockIdx.z];
    int bx = blockIdx.x * 32, by = blockIdx.y * 32;
    int x = threadIdx.x, y = threadIdx.y;
#pragma unroll
    for (int j = 0; j < 32; j += 8)
        t[y + j][x] = in[(size_t)(by + y + j) * E + bx + x];
    __syncthreads();
#pragma unroll
    for (int j = 0; j < 32; j += 8)
        out[(size_t)(bx + y + j) * E + by + x] = __float2half(t[x][y + j]);
}

__global__ void __launch_bounds__(256)
transpose_h_kernel(const float* __restrict__ in, __half* __restrict__ out,
                   int R, int C)
{
    __shared__ float t[32][33];
    int bx = blockIdx.x * 32, by = blockIdx.y * 32;
    int x = threadIdx.x, y = threadIdx.y;
#pragma unroll
    for (int j = 0; j < 32; j += 8)
        t[y + j][x] = in[(size_t)(by + y + j) * C + bx + x];
    __syncthreads();
#pragma unroll
    for (int j = 0; j < 32; j += 8)
        out[(size_t)(bx + y + j) * R + by + x] = __float2half(t[x][y + j]);
}

// ---------------------------------------------------------------------------
// Dual fp32 -> fp16 convert (x and context in one launch)
// ---------------------------------------------------------------------------
__global__ void __launch_bounds__(256)
conv2_h_kernel(const float* __restrict__ a, __half* __restrict__ ah,
               const float* __restrict__ b, __half* __restrict__ bh, int n)
{
    int i = (blockIdx.x * 256 + threadIdx.x) * 4;
    if (i < n) {
        const float* src = blockIdx.y ? b : a;
        __half* dst = blockIdx.y ? bh : ah;
        float4 v = *(const float4*)(src + i);
        __half2 h0 = __floats2half2_rn(v.x, v.y);
        __half2 h1 = __floats2half2_rn(v.z, v.w);
        *(__half2*)(dst + i) = h0;
        *(__half2*)(dst + i + 2) = h1;
    }
}

// ---------------------------------------------------------------------------
// Fused residual + LayerNorm (+ optional fp16 plane)
// ---------------------------------------------------------------------------
__global__ void __launch_bounds__(256)
ln_residual_kernel(const float* __restrict__ X, const float* __restrict__ R,
                   const float* __restrict__ G, const float* __restrict__ Bt,
                   float* __restrict__ Out, __half* __restrict__ Oh)
{
    const int N = E;
    int row = blockIdx.x;
    int tid = threadIdx.x;
    int lane = tid & 31, wid = tid >> 5;
    __shared__ float sm[8];
    __shared__ float stats[2];

    float v[4];
    float s = 0.f;
#pragma unroll
    for (int i = 0; i < 4; i++) {
        int idx = tid + i * 256;
        v[i] = X[(size_t)row * N + idx] + R[(size_t)row * N + idx];
        s += v[i];
    }
#pragma unroll
    for (int off = 16; off > 0; off >>= 1) s += __shfl_down_sync(0xffffffffu, s, off);
    if (lane == 0) sm[wid] = s;
    __syncthreads();
    if (tid == 0) {
        float t = 0.f;
#pragma unroll
        for (int i = 0; i < 8; i++) t += sm[i];
        stats[0] = t * (1.f / N);
    }
    __syncthreads();
    float mu = stats[0];

    float vs = 0.f;
#pragma unroll
    for (int i = 0; i < 4; i++) {
        float d = v[i] - mu;
        vs += d * d;
    }
#pragma unroll
    for (int off = 16; off > 0; off >>= 1) vs += __shfl_down_sync(0xffffffffu, vs, off);
    __syncthreads();
    if (lane == 0) sm[wid] = vs;
    __syncthreads();
    if (tid == 0) {
        float t = 0.f;
#pragma unroll
        for (int i = 0; i < 8; i++) t += sm[i];
        stats[1] = rsqrtf(t * (1.f / N) + LN_EPS);
    }
    __syncthreads();
    float rstd = stats[1];

#pragma unroll
    for (int i = 0; i < 4; i++) {
        int idx = tid + i * 256;
        float y = (v[i] - mu) * rstd * G[idx] + Bt[idx];
        Out[(size_t)row * N + idx] = y;
        if (Oh) Oh[(size_t)row * N + idx] = __float2half(y);
    }
}

// ---------------------------------------------------------------------------
// Launch
// ---------------------------------------------------------------------------
extern "C" void kernel_launch(void* const* d_in, const int* in_sizes, int n_in,
                              void* d_out, int out_size)
{
    const float* x       = (const float*)d_in[0];
    const float* context = (const float*)d_in[1];
    const float* sa_wq = (const float*)d_in[2];
    const float* sa_wk = (const float*)d_in[3];
    const float* sa_wv = (const float*)d_in[4];
    const float* sa_wo = (const float*)d_in[5];
    const float* sa_bo = (const float*)d_in[6];
    const float* ca_wq = (const float*)d_in[7];
    const float* ca_wk = (const float*)d_in[8];
    const float* ca_wv = (const float*)d_in[9];
    const float* ca_wo = (const float*)d_in[10];
    const float* ca_bo = (const float*)d_in[11];
    const float* n1_g  = (const float*)d_in[12];
    const float* n1_b  = (const float*)d_in[13];
    const float* n2_g  = (const float*)d_in[14];
    const float* n2_b  = (const float*)d_in[15];
    const float* n3_g  = (const float*)d_in[16];
    const float* n3_b  = (const float*)d_in[17];
    const float* ff_w1 = (const float*)d_in[18];
    const float* ff_b1 = (const float*)d_in[19];
    const float* ff_w2 = (const float*)d_in[20];
    const float* ff_b2 = (const float*)d_in[21];
    float* out = (float*)d_out;

    float *tmp_, *x1f_, *x2f_;
    cudaGetSymbolAddress((void**)&tmp_, g_tmp);
    cudaGetSymbolAddress((void**)&x1f_, g_x1f);
    cudaGetSymbolAddress((void**)&x2f_, g_x2f);

    __half *qh, *kh, *vh, *ath;
    cudaGetSymbolAddress((void**)&qh,  g_qh);
    cudaGetSymbolAddress((void**)&kh,  g_kh);
    cudaGetSymbolAddress((void**)&vh,  g_vh);
    cudaGetSymbolAddress((void**)&ath, g_ath);

    __half *xh, *ctxh, *x1h, *x2h, *ffh;
    cudaGetSymbolAddress((void**)&xh,   g_xh);
    cudaGetSymbolAddress((void**)&ctxh, g_ctxh);
    cudaGetSymbolAddress((void**)&x1h,  g_x1h);
    cudaGetSymbolAddress((void**)&x2h,  g_x2h);
    cudaGetSymbolAddress((void**)&ffh,  g_ffh);

    __half *wqkv, *wqca, *wkvca, *wot, *cwot, *w1t, *w2t;
    cudaGetSymbolAddress((void**)&wqkv,  g_wqkv_sa);
    cudaGetSymbolAddress((void**)&wqca,  g_wq_ca);
    cudaGetSymbolAddress((void**)&wkvca, g_wkv_ca);
    cudaGetSymbolAddress((void**)&wot,   g_sa_wot);
    cudaGetSymbolAddress((void**)&cwot,  g_ca_wot);
    cudaGetSymbolAddress((void**)&w1t,   g_w1t);
    cudaGetSymbolAddress((void**)&w2t,   g_w2t);

    cudaFuncSetAttribute(hgemm1_kernel,
                         cudaFuncAttributeMaxDynamicSharedMemorySize, HG1_SMEM);

    // 8 E x E transposes in one launch
    TP8 tp;
    tp.s[0] = sa_wq; tp.d[0] = wqkv;
    tp.s[1] = sa_wk; tp.d[1] = wqkv + E * E;
    tp.s[2] = sa_wv; tp.d[2] = wqkv + 2 * E * E;
    tp.s[3] = sa_wo; tp.d[3] = wot;
    tp.s[4] = ca_wq; tp.d[4] = wqca;
    tp.s[5] = ca_wk; tp.d[5] = wkvca;
    tp.s[6] = ca_wv; tp.d[6] = wkvca + E * E;
    tp.s[7] = ca_wo; tp.d[7] = cwot;
    dim3 tB(32, 8);
    transpose8_kernel<<<dim3(E / 32, E / 32, 8), tB>>>(tp);
    transpose_h_kernel<<<dim3(HID / 32, E / 32), tB>>>(ff_w1, w1t, E, HID);
    transpose_h_kernel<<<dim3(E / 32, HID / 32), tB>>>(ff_w2, w2t, HID, E);

    int nElem = M_ROWS * E;
    conv2_h_kernel<<<dim3(nElem / 1024, 2), 256>>>(x, xh, context, ctxh, nElem);

    dim3 gQKV(3 * E / 128, M_ROWS / 128);   // 24 x 32
    dim3 gKV(2 * E / 128, M_ROWS / 128);    // 16 x 32
    dim3 gE(E / 128, M_ROWS / 128);         // 8 x 32
    dim3 gH(HID / 128, M_ROWS / 128);       // 32 x 32
    dim3 gFA(BATCH * NH, T / 64);

    // ---- Self-attention ----
    hgemm1_kernel<<<gQKV, 256, HG1_SMEM>>>(xh, wqkv, nullptr, nullptr,
                                           qh, kh, vh, 8, E, M_ROWS, 3 * E, E, 0);
    fa_mma_kernel<<<gFA, 128>>>(qh, kh, vh, ath, 1);
    hgemm1_kernel<<<gE, 256, HG1_SMEM>>>(ath, wot, sa_bo, tmp_,
                                         nullptr, nullptr, nullptr, 8, E, M_ROWS, E, E, 0);
    ln_residual_kernel<<<M_ROWS, 256>>>(x, tmp_, n1_g, n1_b, x1f_, x1h);

    // ---- Cross-attention ----
    hgemm1_kernel<<<gE, 256, HG1_SMEM>>>(x1h, wqca, nullptr, nullptr,
                                         qh, nullptr, nullptr, 8, E, M_ROWS, E, E, 0);
    hgemm1_kernel<<<gKV, 256, HG1_SMEM>>>(ctxh, wkvca, nullptr, nullptr,
                                          kh, vh, nullptr, 8, E, M_ROWS, 2 * E, E, 0);
    fa_mma_kernel<<<gFA, 128>>>(qh, kh, vh, ath, 0);
    hgemm1_kernel<<<gE, 256, HG1_SMEM>>>(ath, cwot, ca_bo, tmp_,
                                         nullptr, nullptr, nullptr, 8, E, M_ROWS, E, E, 0);
    ln_residual_kernel<<<M_ROWS, 256>>>(x1f_, tmp_, n2_g, n2_b, x2f_, x2h);

    // ---- FFN (single-plane) ----
    hgemm1_kernel<<<gH, 256, HG1_SMEM>>>(x2h, w1t, ff_b1, nullptr,
                                         ffh, nullptr, nullptr, 32, HID, M_ROWS, HID, E, 1);
    hgemm1_kernel<<<gE, 256, HG1_SMEM>>>(ffh, w2t, ff_b2, tmp_,
                                         nullptr, nullptr, nullptr, 8, E, M_ROWS, E, HID, 0);
    ln_residual_kernel<<<M_ROWS, 256>>>(x2f_, tmp_, n3_g, n3_b, out, nullptr);
}

// round 7
// speedup vs baseline: 8.7866x; 1.0191x over previous
#include <cuda_runtime.h>
#include <cuda_fp16.h>
#include <math.h>
#include <stdint.h>

// Problem constants
#define BATCH 4
#define T 1024
#define E 1024
#define NH 16
#define HS 64
#define HID 4096
#define M_ROWS (BATCH * T)   // 4096
#define LN_EPS 1e-5f
#define ATT_SCALE 0.03125f   // E^-0.25 on q and k each -> E^-0.5 on dot
#define LOG2E 1.4426950408889634f

// ---------------------------------------------------------------------------
// Scratch (__device__ globals; no allocation allowed)
// ---------------------------------------------------------------------------
__device__ float  g_tmp[M_ROWS * E];
__device__ float  g_x1f[M_ROWS * E];
__device__ float  g_x2f[M_ROWS * E];
__device__ __half g_qh[M_ROWS * E], g_kh[M_ROWS * E], g_vh[M_ROWS * E];
__device__ __half g_ath[M_ROWS * E];
__device__ __half g_xh[M_ROWS * E];
__device__ __half g_ctxh[M_ROWS * E];
__device__ __half g_x1h[M_ROWS * E];
__device__ __half g_x2h[M_ROWS * E];
__device__ __half g_ffh[M_ROWS * HID];
// fp16 transposed weights [N,K] (QKV packed for fused projections)
__device__ __half g_wqkv_sa[3 * E * E];         // wq^T | wk^T | wv^T
__device__ __half g_wqkv_ca[3 * E * E];         // wq^T | wk^T | wv^T
__device__ __half g_sa_wot[E * E], g_ca_wot[E * E];
__device__ __half g_w1t[HID * E], g_w2t[E * HID];

// ---------------------------------------------------------------------------
// PTX helpers (sm_80+-compatible: cp.async, ldmatrix, mma.sync)
// ---------------------------------------------------------------------------
__device__ __forceinline__ uint32_t smem_u32(const void* p) {
    uint32_t a;
    asm("{ .reg .u64 t; cvta.to.shared.u64 t, %1; cvt.u32.u64 %0, t; }"
        : "=r"(a) : "l"(p));
    return a;
}

#define CP_ASYNC16(saddr, gptr) \
    asm volatile("cp.async.cg.shared.global [%0], [%1], 16;" \
        :: "r"(saddr), "l"(gptr) : "memory")
#define CP_COMMIT()  asm volatile("cp.async.commit_group;" ::: "memory")
#define CP_WAIT0()   asm volatile("cp.async.wait_group 0;" ::: "memory")
#define CP_WAIT1()   asm volatile("cp.async.wait_group 1;" ::: "memory")

#define LDSM4(r, addr) \
    asm volatile("ldmatrix.sync.aligned.m8n8.x4.shared.b16 {%0,%1,%2,%3}, [%4];" \
        : "=r"((r)[0]), "=r"((r)[1]), "=r"((r)[2]), "=r"((r)[3]) : "r"(addr))
#define LDSM2(r, addr) \
    asm volatile("ldmatrix.sync.aligned.m8n8.x2.shared.b16 {%0,%1}, [%2];" \
        : "=r"((r)[0]), "=r"((r)[1]) : "r"(addr))
#define LDSM4T(r, addr) \
    asm volatile("ldmatrix.sync.aligned.m8n8.x4.trans.shared.b16 {%0,%1,%2,%3}, [%4];" \
        : "=r"((r)[0]), "=r"((r)[1]), "=r"((r)[2]), "=r"((r)[3]) : "r"(addr))

__device__ __forceinline__ void mma16816(float* c, const uint32_t* a, const uint32_t* b) {
    asm volatile(
        "mma.sync.aligned.m16n8k16.row.col.f32.f16.f16.f32 "
        "{%0,%1,%2,%3}, {%4,%5,%6,%7}, {%8,%9}, {%0,%1,%2,%3};"
        : "+f"(c[0]), "+f"(c[1]), "+f"(c[2]), "+f"(c[3])
        : "r"(a[0]), "r"(a[1]), "r"(a[2]), "r"(a[3]), "r"(b[0]), "r"(b[1]));
}

// ===========================================================================
// Single-plane HGEMM: C = A[M,K] @ Bt[N,K]^T (+bias)(+relu)
// A selected per N-tile: bx < a2Start -> Ah, else A2 (lets one launch cover
// GEMMs sharing B layout but different A). Output: fp32 C32 OR fp16 into up
// to 3 dest buffers selected by bx/dstTiles (leading dim outLd).
// Tile 128x128x64, 256 threads, 3-stage cp.async (96KB smem, 2 CTA/SM),
// single __syncthreads per ktile.
// ===========================================================================
#define HG1_STAGE 32768
#define HG1_SMEM  (3 * HG1_STAGE)

__global__ void __launch_bounds__(256, 2)
hgemm1_kernel(const __half* __restrict__ Ah, const __half* __restrict__ A2,
              int a2Start,
              const __half* __restrict__ Bt, const float* __restrict__ bias,
              float* __restrict__ C32,
              __half* __restrict__ D0, __half* __restrict__ D1, __half* __restrict__ D2,
              int dstTiles, int outLd, int N, int K, int relu)
{
    extern __shared__ char smem[];
    uint32_t sb = smem_u32(smem);
    int tid = threadIdx.x;
    int lane = tid & 31;
    int wid = tid >> 5;
    int wm = wid & 1, wn = wid >> 1;
    int bx = blockIdx.x, by = blockIdx.y;

    const __half* Abase = (bx < a2Start) ? Ah : A2;
    const __half* gA = Abase + (size_t)by * 128 * K;
    const __half* gB = Bt + (size_t)bx * 128 * K;

    int lrow = tid >> 3;
    int lch = tid & 7;
    uint32_t soff[4];
#pragma unroll
    for (int i = 0; i < 4; i++) {
        int r = lrow + 32 * i;
        soff[i] = (uint32_t)(r * 128 + ((lch ^ (r & 7)) * 16));
    }

    uint32_t aOff[4], aX[4], bOff[4], bX[4];
#pragma unroll
    for (int mf = 0; mf < 4; mf++) {
        int r = wm * 64 + mf * 16 + (lane & 15);
        aOff[mf] = r * 128; aX[mf] = r & 7;
    }
#pragma unroll
    for (int nf = 0; nf < 4; nf++) {
        int r = wn * 32 + nf * 8 + (lane & 7);
        bOff[nf] = r * 128; bX[nf] = r & 7;
    }
    int aSel = lane >> 4;
    int bSel = (lane >> 3) & 1;

    float acc[4][4][4];
#pragma unroll
    for (int mf = 0; mf < 4; mf++)
#pragma unroll
        for (int nf = 0; nf < 4; nf++)
#pragma unroll
            for (int r = 0; r < 4; r++) acc[mf][nf][r] = 0.f;

    const int KT = K >> 6;

    // Prologue: stage ktiles 0 and 1 into buffers 0 and 1
#pragma unroll
    for (int p = 0; p < 2; p++) {
        uint32_t st = sb + p * HG1_STAGE;
        int k0 = p << 6;
#pragma unroll
        for (int i = 0; i < 4; i++) {
            int r = lrow + 32 * i;
            CP_ASYNC16(st + soff[i],         gA + (size_t)r * K + k0 + lch * 8);
            CP_ASYNC16(st + 16384 + soff[i], gB + (size_t)r * K + k0 + lch * 8);
        }
        CP_COMMIT();
    }

    int cur = 0;   // buffer for current ktile
    int pf = 2;    // buffer for ktile kt+2
    for (int kt = 0; kt < KT; kt++) {
        if (kt + 2 < KT) { CP_WAIT1(); } else { CP_WAIT0(); }
        __syncthreads();

        if (kt + 2 < KT) {
            uint32_t st = sb + pf * HG1_STAGE;
            int k0 = (kt + 2) << 6;
#pragma unroll
            for (int i = 0; i < 4; i++) {
                int r = lrow + 32 * i;
                CP_ASYNC16(st + soff[i],         gA + (size_t)r * K + k0 + lch * 8);
                CP_ASYNC16(st + 16384 + soff[i], gB + (size_t)r * K + k0 + lch * 8);
            }
            CP_COMMIT();
        }

        uint32_t aBase = sb + cur * HG1_STAGE;
        uint32_t bBase = aBase + 16384;

#pragma unroll
        for (int ks = 0; ks < 4; ks++) {
            int cA = ks * 2 + aSel;
            int cB = ks * 2 + bSel;
            uint32_t a[4][4], b[4][2];
#pragma unroll
            for (int mf = 0; mf < 4; mf++)
                LDSM4(a[mf], aBase + aOff[mf] + ((cA ^ aX[mf]) << 4));
#pragma unroll
            for (int nf = 0; nf < 4; nf++)
                LDSM2(b[nf], bBase + bOff[nf] + ((cB ^ bX[nf]) << 4));
#pragma unroll
            for (int mf = 0; mf < 4; mf++)
#pragma unroll
                for (int nf = 0; nf < 4; nf++)
                    mma16816(acc[mf][nf], a[mf], b[nf]);
        }

        cur = (cur == 2) ? 0 : cur + 1;
        pf  = (pf == 2) ? 0 : pf + 1;
    }

    int g = lane >> 2, tig = lane & 3;
    int which = bx / dstTiles;
    int lbx = bx - which * dstTiles;
    __half* D = (which == 0) ? D0 : ((which == 1) ? D1 : D2);
#pragma unroll
    for (int mf = 0; mf < 4; mf++) {
#pragma unroll
        for (int nf = 0; nf < 4; nf++) {
            int r0 = by * 128 + wm * 64 + mf * 16 + g;
            int cl = wn * 32 + nf * 8 + tig * 2;
            int cglob = bx * 128 + cl;
            float b0 = 0.f, b1 = 0.f;
            if (bias) { b0 = bias[cglob]; b1 = bias[cglob + 1]; }
            float v0 = acc[mf][nf][0] + b0, v1 = acc[mf][nf][1] + b1;
            float v2 = acc[mf][nf][2] + b0, v3 = acc[mf][nf][3] + b1;
            if (relu) {
                v0 = fmaxf(v0, 0.f); v1 = fmaxf(v1, 0.f);
                v2 = fmaxf(v2, 0.f); v3 = fmaxf(v3, 0.f);
            }
            if (C32) {
                *(float2*)(C32 + (size_t)r0 * N + cglob) = make_float2(v0, v1);
                *(float2*)(C32 + (size_t)(r0 + 8) * N + cglob) = make_float2(v2, v3);
            } else {
                int c = lbx * 128 + cl;
                *(__half2*)(D + (size_t)r0 * outLd + c) = __floats2half2_rn(v0, v1);
                *(__half2*)(D + (size_t)(r0 + 8) * outLd + c) = __floats2half2_rn(v2, v3);
            }
        }
    }
}

// ---------------------------------------------------------------------------
// Tensor-core flash attention. grid (BATCH*NH, T/64), 128 threads.
// Softmax in log2 domain (exp2f = bare MUFU EX2).
// ---------------------------------------------------------------------------
__global__ void __launch_bounds__(128)
fa_mma_kernel(const __half* __restrict__ Qm, const __half* __restrict__ Km,
              const __half* __restrict__ Vm, __half* __restrict__ Oh, int causal)
{
    __shared__ __half sQ[64 * 64];
    __shared__ __half sK[2][64 * 64];
    __shared__ __half sV[2][64 * 64];

    int tid = threadIdx.x, lane = tid & 31, w = tid >> 5;
    int g = lane >> 2, tig = lane & 3;
    int bh = blockIdx.x, b = bh >> 4, h = bh & 15;
    int qt = blockIdx.y;

    uint32_t sq = smem_u32(sQ);
    uint32_t skb[2] = { smem_u32(sK[0]), smem_u32(sK[1]) };
    uint32_t svb[2] = { smem_u32(sV[0]), smem_u32(sV[1]) };

    const __half* Qg = Qm + ((size_t)(b * T + qt * 64)) * E + h * HS;
    const __half* K0 = Km + ((size_t)(b * T)) * E + h * HS;
    const __half* V0 = Vm + ((size_t)(b * T)) * E + h * HS;

#pragma unroll
    for (int i = 0; i < 4; i++) {
        int c = tid + i * 128; int r = c >> 3; int ch = c & 7;
        uint32_t off = r * 128 + ((ch ^ (r & 7)) << 4);
        CP_ASYNC16(sq + off, Qg + (size_t)r * E + ch * 8);
        CP_ASYNC16(skb[0] + off, K0 + (size_t)r * E + ch * 8);
        CP_ASYNC16(svb[0] + off, V0 + (size_t)r * E + ch * 8);
    }
    CP_COMMIT();
    CP_WAIT0();
    __syncthreads();

    uint32_t qf[4][4];
    {
        int r = w * 16 + (lane & 15); int sel = lane >> 4; int rx = r & 7;
        uint32_t ro = sq + r * 128;
#pragma unroll
        for (int ks = 0; ks < 4; ks++)
            LDSM4(qf[ks], ro + (((2 * ks + sel) ^ rx) << 4));
    }

    float oacc[8][4];
#pragma unroll
    for (int n = 0; n < 8; n++)
#pragma unroll
        for (int e = 0; e < 4; e++) oacc[n][e] = 0.f;
    float m0 = -1e30f, m1 = -1e30f, l0 = 0.f, l1 = 0.f;

    int nk = causal ? (qt + 1) : (T / 64);
    const float SC2 = ATT_SCALE * LOG2E;   // scores in log2 domain

    for (int kt = 0; kt < nk; kt++) {
        int cur = kt & 1;
        if (kt + 1 < nk) {
            int nst = cur ^ 1;
            const __half* Kg = Km + ((size_t)(b * T + (kt + 1) * 64)) * E + h * HS;
            const __half* Vg = Vm + ((size_t)(b * T + (kt + 1) * 64)) * E + h * HS;
#pragma unroll
            for (int i = 0; i < 4; i++) {
                int c = tid + i * 128; int r = c >> 3; int ch = c & 7;
                uint32_t off = r * 128 + ((ch ^ (r & 7)) << 4);
                CP_ASYNC16(skb[nst] + off, Kg + (size_t)r * E + ch * 8);
                CP_ASYNC16(svb[nst] + off, Vg + (size_t)r * E + ch * 8);
            }
            CP_COMMIT();
        }

        float sacc[8][4];
#pragma unroll
        for (int n = 0; n < 8; n++)
#pragma unroll
            for (int e = 0; e < 4; e++) sacc[n][e] = 0.f;

        uint32_t skc = skb[cur], svc = svb[cur];
#pragma unroll
        for (int ks = 0; ks < 4; ks++) {
            uint32_t kb[8][2];
            int rl = lane & 7, sel = (lane >> 3) & 1;
#pragma unroll
            for (int n = 0; n < 8; n++) {
                int rr = n * 8 + rl;
                LDSM2(kb[n], skc + rr * 128 + (((2 * ks + sel) ^ (rr & 7)) << 4));
            }
#pragma unroll
            for (int n = 0; n < 8; n++) mma16816(sacc[n], qf[ks], kb[n]);
        }

#pragma unroll
        for (int n = 0; n < 8; n++)
#pragma unroll
            for (int e = 0; e < 4; e++) sacc[n][e] *= SC2;
        if (causal && kt == qt) {
            int row0 = w * 16 + g;
#pragma unroll
            for (int n = 0; n < 8; n++) {
                int c0 = n * 8 + tig * 2;
                if (c0     > row0)     sacc[n][0] = -1e30f;
                if (c0 + 1 > row0)     sacc[n][1] = -1e30f;
                if (c0     > row0 + 8) sacc[n][2] = -1e30f;
                if (c0 + 1 > row0 + 8) sacc[n][3] = -1e30f;
            }
        }

        float mx0 = -1e30f, mx1 = -1e30f;
#pragma unroll
        for (int n = 0; n < 8; n++) {
            mx0 = fmaxf(mx0, fmaxf(sacc[n][0], sacc[n][1]));
            mx1 = fmaxf(mx1, fmaxf(sacc[n][2], sacc[n][3]));
        }
        mx0 = fmaxf(mx0, __shfl_xor_sync(0xffffffffu, mx0, 1));
        mx0 = fmaxf(mx0, __shfl_xor_sync(0xffffffffu, mx0, 2));
        mx1 = fmaxf(mx1, __shfl_xor_sync(0xffffffffu, mx1, 1));
        mx1 = fmaxf(mx1, __shfl_xor_sync(0xffffffffu, mx1, 2));
        float mn0 = fmaxf(m0, mx0), mn1 = fmaxf(m1, mx1);
        float a0 = exp2f(m0 - mn0), a1 = exp2f(m1 - mn1);
        m0 = mn0; m1 = mn1;

        float ps0 = 0.f, ps1 = 0.f;
        uint32_t pf[4][4];
#pragma unroll
        for (int n = 0; n < 8; n++) {
            float p0 = exp2f(sacc[n][0] - mn0), p1 = exp2f(sacc[n][1] - mn0);
            float p2 = exp2f(sacc[n][2] - mn1), p3 = exp2f(sacc[n][3] - mn1);
            ps0 += p0 + p1; ps1 += p2 + p3;
            __half2 h01 = __floats2half2_rn(p0, p1);
            __half2 h23 = __floats2half2_rn(p2, p3);
            int ks = n >> 1, hi = (n & 1) * 2;
            pf[ks][hi]     = *(uint32_t*)&h01;
            pf[ks][hi + 1] = *(uint32_t*)&h23;
        }
        l0 = l0 * a0 + ps0;
        l1 = l1 * a1 + ps1;
#pragma unroll
        for (int n = 0; n < 8; n++) {
            oacc[n][0] *= a0; oacc[n][1] *= a0;
            oacc[n][2] *= a1; oacc[n][3] *= a1;
        }

        {
            int rl = lane & 15, cs = lane >> 4;
#pragma unroll
            for (int np = 0; np < 4; np++) {
#pragma unroll
                for (int ks = 0; ks < 4; ks++) {
                    uint32_t vb[4];
                    int rr = ks * 16 + rl;
                    int ch = np * 2 + cs;
                    LDSM4T(vb, svc + rr * 128 + ((ch ^ (rr & 7)) << 4));
                    mma16816(oacc[2 * np],     pf[ks], vb);
                    mma16816(oacc[2 * np + 1], pf[ks], vb + 2);
                }
            }
        }

        CP_WAIT0();
        __syncthreads();
    }

    l0 += __shfl_xor_sync(0xffffffffu, l0, 1);
    l0 += __shfl_xor_sync(0xffffffffu, l0, 2);
    l1 += __shfl_xor_sync(0xffffffffu, l1, 1);
    l1 += __shfl_xor_sync(0xffffffffu, l1, 2);
    float i0 = 1.f / l0, i1 = 1.f / l1;

    size_t base0 = ((size_t)(b * T + qt * 64 + w * 16 + g)) * E + h * HS;
    size_t base1 = base0 + (size_t)8 * E;
#pragma unroll
    for (int n = 0; n < 8; n++) {
        int c = n * 8 + tig * 2;
        *(__half2*)(Oh + base0 + c) = __floats2half2_rn(oacc[n][0] * i0, oacc[n][1] * i0);
        *(__half2*)(Oh + base1 + c) = __floats2half2_rn(oacc[n][2] * i1, oacc[n][3] * i1);
    }
}

// ---------------------------------------------------------------------------
// Batched weight transpose to fp16 (8 equal E x E matrices, one launch)
// ---------------------------------------------------------------------------
struct TP8 { const float* s[8]; __half* d[8]; };

__global__ void __launch_bounds__(256)
transpose8_kernel(TP8 p)
{
    __shared__ float t[32][33];
    const float* in = p.s[blockIdx.z];
    __half* out = p.d[blockIdx.z];
    int bx = blockIdx.x * 32, by = blockIdx.y * 32;
    int x = threadIdx.x, y = threadIdx.y;
#pragma unroll
    for (int j = 0; j < 32; j += 8)
        t[y + j][x] = in[(size_t)(by + y + j) * E + bx + x];
    __syncthreads();
#pragma unroll
    for (int j = 0; j < 32; j += 8)
        out[(size_t)(bx + y + j) * E + by + x] = __float2half(t[x][y + j]);
}

__global__ void __launch_bounds__(256)
transpose_h_kernel(const float* __restrict__ in, __half* __restrict__ out,
                   int R, int C)
{
    __shared__ float t[32][33];
    int bx = blockIdx.x * 32, by = blockIdx.y * 32;
    int x = threadIdx.x, y = threadIdx.y;
#pragma unroll
    for (int j = 0; j < 32; j += 8)
        t[y + j][x] = in[(size_t)(by + y + j) * C + bx + x];
    __syncthreads();
#pragma unroll
    for (int j = 0; j < 32; j += 8)
        out[(size_t)(bx + y + j) * R + by + x] = __float2half(t[x][y + j]);
}

// ---------------------------------------------------------------------------
// Dual fp32 -> fp16 convert (x and context in one launch)
// ---------------------------------------------------------------------------
__global__ void __launch_bounds__(256)
conv2_h_kernel(const float* __restrict__ a, __half* __restrict__ ah,
               const float* __restrict__ b, __half* __restrict__ bh, int n)
{
    int i = (blockIdx.x * 256 + threadIdx.x) * 4;
    if (i < n) {
        const float* src = blockIdx.y ? b : a;
        __half* dst = blockIdx.y ? bh : ah;
        float4 v = *(const float4*)(src + i);
        __half2 h0 = __floats2half2_rn(v.x, v.y);
        __half2 h1 = __floats2half2_rn(v.z, v.w);
        *(__half2*)(dst + i) = h0;
        *(__half2*)(dst + i + 2) = h1;
    }
}

// ---------------------------------------------------------------------------
// Fused residual + LayerNorm (+ optional fp16 plane)
// ---------------------------------------------------------------------------
__global__ void __launch_bounds__(256)
ln_residual_kernel(const float* __restrict__ X, const float* __restrict__ R,
                   const float* __restrict__ G, const float* __restrict__ Bt,
                   float* __restrict__ Out, __half* __restrict__ Oh)
{
    const int N = E;
    int row = blockIdx.x;
    int tid = threadIdx.x;
    int lane = tid & 31, wid = tid >> 5;
    __shared__ float sm[8];
    __shared__ float stats[2];

    float v[4];
    float s = 0.f;
#pragma unroll
    for (int i = 0; i < 4; i++) {
        int idx = tid + i * 256;
        v[i] = X[(size_t)row * N + idx] + R[(size_t)row * N + idx];
        s += v[i];
    }
#pragma unroll
    for (int off = 16; off > 0; off >>= 1) s += __shfl_down_sync(0xffffffffu, s, off);
    if (lane == 0) sm[wid] = s;
    __syncthreads();
    if (tid == 0) {
        float t = 0.f;
#pragma unroll
        for (int i = 0; i < 8; i++) t += sm[i];
        stats[0] = t * (1.f / N);
    }
    __syncthreads();
    float mu = stats[0];

    float vs = 0.f;
#pragma unroll
    for (int i = 0; i < 4; i++) {
        float d = v[i] - mu;
        vs += d * d;
    }
#pragma unroll
    for (int off = 16; off > 0; off >>= 1) vs += __shfl_down_sync(0xffffffffu, vs, off);
    __syncthreads();
    if (lane == 0) sm[wid] = vs;
    __syncthreads();
    if (tid == 0) {
        float t = 0.f;
#pragma unroll
        for (int i = 0; i < 8; i++) t += sm[i];
        stats[1] = rsqrtf(t * (1.f / N) + LN_EPS);
    }
    __syncthreads();
    float rstd = stats[1];

#pragma unroll
    for (int i = 0; i < 4; i++) {
        int idx = tid + i * 256;
        float y = (v[i] - mu) * rstd * G[idx] + Bt[idx];
        Out[(size_t)row * N + idx] = y;
        if (Oh) Oh[(size_t)row * N + idx] = __float2half(y);
    }
}

// ---------------------------------------------------------------------------
// Launch
// ---------------------------------------------------------------------------
extern "C" void kernel_launch(void* const* d_in, const int* in_sizes, int n_in,
                              void* d_out, int out_size)
{
    const float* x       = (const float*)d_in[0];
    const float* context = (const float*)d_in[1];
    const float* sa_wq = (const float*)d_in[2];
    const float* sa_wk = (const float*)d_in[3];
    const float* sa_wv = (const float*)d_in[4];
    const float* sa_wo = (const float*)d_in[5];
    const float* sa_bo = (const float*)d_in[6];
    const float* ca_wq = (const float*)d_in[7];
    const float* ca_wk = (const float*)d_in[8];
    const float* ca_wv = (const float*)d_in[9];
    const float* ca_wo = (const float*)d_in[10];
    const float* ca_bo = (const float*)d_in[11];
    const float* n1_g  = (const float*)d_in[12];
    const float* n1_b  = (const float*)d_in[13];
    const float* n2_g  = (const float*)d_in[14];
    const float* n2_b  = (const float*)d_in[15];
    const float* n3_g  = (const float*)d_in[16];
    const float* n3_b  = (const float*)d_in[17];
    const float* ff_w1 = (const float*)d_in[18];
    const float* ff_b1 = (const float*)d_in[19];
    const float* ff_w2 = (const float*)d_in[20];
    const float* ff_b2 = (const float*)d_in[21];
    float* out = (float*)d_out;

    float *tmp_, *x1f_, *x2f_;
    cudaGetSymbolAddress((void**)&tmp_, g_tmp);
    cudaGetSymbolAddress((void**)&x1f_, g_x1f);
    cudaGetSymbolAddress((void**)&x2f_, g_x2f);

    __half *qh, *kh, *vh, *ath;
    cudaGetSymbolAddress((void**)&qh,  g_qh);
    cudaGetSymbolAddress((void**)&kh,  g_kh);
    cudaGetSymbolAddress((void**)&vh,  g_vh);
    cudaGetSymbolAddress((void**)&ath, g_ath);

    __half *xh, *ctxh, *x1h, *x2h, *ffh;
    cudaGetSymbolAddress((void**)&xh,   g_xh);
    cudaGetSymbolAddress((void**)&ctxh, g_ctxh);
    cudaGetSymbolAddress((void**)&x1h,  g_x1h);
    cudaGetSymbolAddress((void**)&x2h,  g_x2h);
    cudaGetSymbolAddress((void**)&ffh,  g_ffh);

    __half *wqkv, *wqkvca, *wot, *cwot, *w1t, *w2t;
    cudaGetSymbolAddress((void**)&wqkv,   g_wqkv_sa);
    cudaGetSymbolAddress((void**)&wqkvca, g_wqkv_ca);
    cudaGetSymbolAddress((void**)&wot,    g_sa_wot);
    cudaGetSymbolAddress((void**)&cwot,   g_ca_wot);
    cudaGetSymbolAddress((void**)&w1t,    g_w1t);
    cudaGetSymbolAddress((void**)&w2t,    g_w2t);

    cudaFuncSetAttribute(hgemm1_kernel,
                         cudaFuncAttributeMaxDynamicSharedMemorySize, HG1_SMEM);

    // 8 E x E transposes in one launch
    TP8 tp;
    tp.s[0] = sa_wq; tp.d[0] = wqkv;
    tp.s[1] = sa_wk; tp.d[1] = wqkv + E * E;
    tp.s[2] = sa_wv; tp.d[2] = wqkv + 2 * E * E;
    tp.s[3] = sa_wo; tp.d[3] = wot;
    tp.s[4] = ca_wq; tp.d[4] = wqkvca;
    tp.s[5] = ca_wk; tp.d[5] = wqkvca + E * E;
    tp.s[6] = ca_wv; tp.d[6] = wqkvca + 2 * E * E;
    tp.s[7] = ca_wo; tp.d[7] = cwot;
    dim3 tB(32, 8);
    transpose8_kernel<<<dim3(E / 32, E / 32, 8), tB>>>(tp);
    transpose_h_kernel<<<dim3(HID / 32, E / 32), tB>>>(ff_w1, w1t, E, HID);
    transpose_h_kernel<<<dim3(E / 32, HID / 32), tB>>>(ff_w2, w2t, HID, E);

    int nElem = M_ROWS * E;
    conv2_h_kernel<<<dim3(nElem / 1024, 2), 256>>>(x, xh, context, ctxh, nElem);

    dim3 gQKV(3 * E / 128, M_ROWS / 128);   // 24 x 32
    dim3 gE(E / 128, M_ROWS / 128);         // 8 x 32
    dim3 gH(HID / 128, M_ROWS / 128);       // 32 x 32
    dim3 gFA(BATCH * NH, T / 64);

    // ---- Self-attention ----
    hgemm1_kernel<<<gQKV, 256, HG1_SMEM>>>(xh, nullptr, 1 << 30, wqkv, nullptr, nullptr,
                                           qh, kh, vh, 8, E, 3 * E, E, 0);
    fa_mma_kernel<<<gFA, 128>>>(qh, kh, vh, ath, 1);
    hgemm1_kernel<<<gE, 256, HG1_SMEM>>>(ath, nullptr, 1 << 30, wot, sa_bo, tmp_,
                                         nullptr, nullptr, nullptr, 8, E, E, E, 0);
    ln_residual_kernel<<<M_ROWS, 256>>>(x, tmp_, n1_g, n1_b, x1f_, x1h);

    // ---- Cross-attention (q from x1h, k/v from ctxh; one launch) ----
    hgemm1_kernel<<<gQKV, 256, HG1_SMEM>>>(x1h, ctxh, 8, wqkvca, nullptr, nullptr,
                                           qh, kh, vh, 8, E, 3 * E, E, 0);
    fa_mma_kernel<<<gFA, 128>>>(qh, kh, vh, ath, 0);
    hgemm1_kernel<<<gE, 256, HG1_SMEM>>>(ath, nullptr, 1 << 30, cwot, ca_bo, tmp_,
                                         nullptr, nullptr, nullptr, 8, E, E, E, 0);
    ln_residual_kernel<<<M_ROWS, 256>>>(x1f_, tmp_, n2_g, n2_b, x2f_, x2h);

    // ---- FFN ----
    hgemm1_kernel<<<gH, 256, HG1_SMEM>>>(x2h, nullptr, 1 << 30, w1t, ff_b1, nullptr,
                                         ffh, nullptr, nullptr, 32, HID, HID, E, 1);
    hgemm1_kernel<<<gE, 256, HG1_SMEM>>>(ffh, nullptr, 1 << 30, w2t, ff_b2, tmp_,
                                         nullptr, nullptr, nullptr, 8, E, E, HID, 0);
    ln_residual_kernel<<<M_ROWS, 256>>>(x2f_, tmp_, n3_g, n3_b, out, nullptr);
}